// round 6
// baseline (speedup 1.0000x reference)
#include <cuda_runtime.h>
#include <cstdint>

// ---------------------------------------------------------------------------
// Problem constants
// ---------------------------------------------------------------------------
#define DIN_   2048
#define NQ_    4096
#define NK_    1024
#define NTOT_  5120
#define DHEAD_ 128
#define NHEAD_ 8
#define NGROUP_ 4
#define SINK_  16
#define SMAX_  32768

__device__ float g_qbuf[(size_t)SMAX_ * NQ_];   // 512 MB scratch
__device__ float g_kbuf[(size_t)SMAX_ * NK_];   // 128 MB scratch

// ---------------------------------------------------------------------------
// GEMM: C[S,5120] = hidden[S,2048] @ [Wq;Wk]^T (+bq on q part)
// legacy mma.sync m16n8k8 tf32 (raw fp32 bits; RMSNorm cancels the uniform
// truncation bias). 512 threads / 16 warps, warp tile 32x64,
// BM=128 BN=256 BK=32, 3-stage cp.async ring.
// ---------------------------------------------------------------------------
#define BM 128
#define BN 256
#define BK 32
#define NSTAGE 3
#define A_BYTES (128 * 128)            // 128 rows x 32 floats (128B)
#define B_BYTES (256 * 128)            // 256 rows x 32 floats
#define SLOT_BYTES (A_BYTES + B_BYTES) // 48 KB
#define SMEM_TOTAL (NSTAGE * SLOT_BYTES)   // 144 KB
#define GTHREADS 512

__device__ __forceinline__ uint32_t smem_to_u32(const void* p) {
    uint32_t a;
    asm("{ .reg .u64 t; cvta.to.shared.u64 t, %1; cvt.u32.u64 %0, t; }" : "=r"(a) : "l"(p));
    return a;
}

__device__ __forceinline__ void cp16s(uint32_t dst, const float* src) {
    asm volatile("cp.async.cg.shared.global [%0], [%1], 16;\n" :: "r"(dst), "l"(src));
}

__device__ __forceinline__ void ldsm_x4(uint32_t& r0, uint32_t& r1, uint32_t& r2,
                                        uint32_t& r3, uint32_t addr) {
    asm volatile("ldmatrix.sync.aligned.m8n8.x4.shared.b16 {%0,%1,%2,%3}, [%4];"
                 : "=r"(r0), "=r"(r1), "=r"(r2), "=r"(r3) : "r"(addr));
}

__device__ __forceinline__ void mma_tf32(float c[4], const uint32_t a[4],
                                         const uint32_t b0, const uint32_t b1) {
    asm volatile(
        "mma.sync.aligned.m16n8k8.row.col.f32.tf32.tf32.f32 "
        "{%0,%1,%2,%3}, {%4,%5,%6,%7}, {%8,%9}, {%0,%1,%2,%3};\n"
        : "+f"(c[0]), "+f"(c[1]), "+f"(c[2]), "+f"(c[3])
        : "r"(a[0]), "r"(a[1]), "r"(a[2]), "r"(a[3]), "r"(b0), "r"(b1));
}

// swizzled byte offset of (row, chunk); chunk = 16B unit within the 128B row
__device__ __forceinline__ uint32_t swz(int row, int chunk) {
    return (uint32_t)(row * 128 + ((chunk ^ (row & 7)) << 4));
}

__global__ void __launch_bounds__(GTHREADS, 1) gemm_qk(
    const float* __restrict__ hidden, const float* __restrict__ Wq,
    const float* __restrict__ Wk, const float* __restrict__ bq)
{
    extern __shared__ char smem[];
    const uint32_t sbase = smem_to_u32(smem);
    const int tid = threadIdx.x;
    const int lane = tid & 31, wid = tid >> 5;
    const int wm = wid >> 2, wn = wid & 3;     // 4x4 warp grid, warp tile 32x64
    const int gid = lane >> 2, tig = lane & 3;

    const int n0 = blockIdx.x * BN;
    const int m0 = blockIdx.y * BM;
    const bool isq = (n0 < NQ_);
    const float* wrow = isq ? (Wq + (size_t)n0 * DIN_) : (Wk + (size_t)(n0 - NQ_) * DIN_);
    const float* arow = hidden + (size_t)m0 * DIN_;

    float acc[2][8][4];
#pragma unroll
    for (int a = 0; a < 2; a++)
#pragma unroll
        for (int b = 0; b < 8; b++)
#pragma unroll
            for (int c = 0; c < 4; c++) acc[a][b][c] = 0.f;

    // ldmatrix per-lane source rows/chunks (stage-invariant parts)
    const int arow_l   = wm * 32 + (lane & 15);                     // + tm*16
    const int achunk_l = lane >> 4;                                 // + 2*kk
    const int brow_l   = wn * 64 + (lane & 7) + ((lane & 16) >> 1); // + np*16
    const int bchunk_l = (lane >> 3) & 1;                           // + 2*kk

    auto load_stage = [&](int s) {
        const uint32_t slot = sbase + (uint32_t)(s % NSTAGE) * SLOT_BYTES;
        const int k0 = s * BK;
#pragma unroll
        for (int i = 0; i < 2; i++) {          // A: 128 rows x 8 chunks = 1024
            int id = tid + i * GTHREADS;
            int r = id >> 3, c = id & 7;
            cp16s(slot + swz(r, c), arow + (size_t)r * DIN_ + k0 + c * 4);
        }
#pragma unroll
        for (int i = 0; i < 4; i++) {          // B: 256 rows x 8 chunks = 2048
            int id = tid + i * GTHREADS;
            int r = id >> 3, c = id & 7;
            cp16s(slot + A_BYTES + swz(r, c), wrow + (size_t)r * DIN_ + k0 + c * 4);
        }
        asm volatile("cp.async.commit_group;\n");
    };

    load_stage(0);
    load_stage(1);

    const int NSTEPS = DIN_ / BK;  // 64
    for (int s = 0; s < NSTEPS; s++) {
        if (s < NSTEPS - 1) asm volatile("cp.async.wait_group 1;\n" ::: "memory");
        else                asm volatile("cp.async.wait_group 0;\n" ::: "memory");
        __syncthreads();

        // prefetch s+2 before compute (slot (s+2)%3 was consumed last iteration)
        if (s + 2 < NSTEPS) load_stage(s + 2);

        const uint32_t slot = sbase + (uint32_t)(s % NSTAGE) * SLOT_BYTES;
#pragma unroll
        for (int kk = 0; kk < 4; kk++) {       // 4 x k8 per stage
            uint32_t af[2][4], bf[4][4];
#pragma unroll
            for (int tm = 0; tm < 2; tm++)
                ldsm_x4(af[tm][0], af[tm][1], af[tm][2], af[tm][3],
                        slot + swz(arow_l + tm * 16, 2 * kk + achunk_l));
#pragma unroll
            for (int np = 0; np < 4; np++)
                ldsm_x4(bf[np][0], bf[np][1], bf[np][2], bf[np][3],
                        slot + A_BYTES + swz(brow_l + np * 16, 2 * kk + bchunk_l));
#pragma unroll
            for (int tm = 0; tm < 2; tm++)
#pragma unroll
                for (int np = 0; np < 4; np++) {
                    mma_tf32(acc[tm][2 * np],     af[tm], bf[np][0], bf[np][1]);
                    mma_tf32(acc[tm][2 * np + 1], af[tm], bf[np][2], bf[np][3]);
                }
        }
    }

    // ---- store (+bq on q part)
    float bq0[8], bq1[8];
#pragma unroll
    for (int tn = 0; tn < 8; tn++) {
        int col = n0 + wn * 64 + tn * 8 + 2 * tig;
        bq0[tn] = isq ? __ldg(bq + col) : 0.f;
        bq1[tn] = isq ? __ldg(bq + col + 1) : 0.f;
    }
    float* obase = isq ? g_qbuf : g_kbuf;
    const int ld = isq ? NQ_ : NK_;
    const int cb = isq ? n0 : (n0 - NQ_);

#pragma unroll
    for (int tm = 0; tm < 2; tm++) {
#pragma unroll
        for (int tn = 0; tn < 8; tn++) {
            int r = m0 + wm * 32 + tm * 16 + gid;
            int c = cb + wn * 64 + tn * 8 + 2 * tig;
            float2 v0 = make_float2(acc[tm][tn][0] + bq0[tn], acc[tm][tn][1] + bq1[tn]);
            float2 v1 = make_float2(acc[tm][tn][2] + bq0[tn], acc[tm][tn][3] + bq1[tn]);
            *reinterpret_cast<float2*>(obase + (size_t)r * ld + c) = v0;
            *reinterpret_cast<float2*>(obase + (size_t)(r + 8) * ld + c) = v1;
        }
    }
}

// ---------------------------------------------------------------------------
// Epilogue: RMSNorm(q), RMSNorm(k), logits, sink gate, mean over groups.
// k_base in 64KB smem ([h][t][lane]:float4); __launch_bounds__(256,3) caps
// registers so 3 blocks/SM actually materialize (24 warps, 37.5% occ).
// ---------------------------------------------------------------------------
#define TOK_PER_BLK 16
#define EPI_SMEM (NHEAD_ * SINK_ * 32 * 16)   // 65536 B

__device__ __forceinline__ float wsum(float v) {
    v += __shfl_xor_sync(0xffffffffu, v, 16);
    v += __shfl_xor_sync(0xffffffffu, v, 8);
    v += __shfl_xor_sync(0xffffffffu, v, 4);
    v += __shfl_xor_sync(0xffffffffu, v, 2);
    v += __shfl_xor_sync(0xffffffffu, v, 1);
    return v;
}

__global__ void __launch_bounds__(256, 3) epilogue_kernel(
    float* __restrict__ out, const float* __restrict__ bvec,
    const float* __restrict__ k_base, const float* __restrict__ qw,
    const float* __restrict__ kw, int nseq)
{
    extern __shared__ float4 kbs[];   // [(h*16+t)*32 + lane] = {d=lane,+32,+64,+96}
    const int tid = threadIdx.x;
    const int lane = tid & 31;
    const int h = tid >> 5;
    const float inv_d = 0.08838834764831845f;

    {
        float* kbf = reinterpret_cast<float*>(kbs);
#pragma unroll
        for (int i = 0; i < 64; i++) {
            int idx = tid + i * 256;               // 0..16383
            int j = idx & 3;
            int ln = (idx >> 2) & 31;
            int ht = idx >> 7;
            kbf[idx] = k_base[(size_t)ht * DHEAD_ + j * 32 + ln];
        }
    }
    __syncthreads();

    const float4* kb4 = kbs + (h * SINK_) * 32 + lane;   // index: + t*32

    float qwr[4], kwr[4];
#pragma unroll
    for (int j = 0; j < 4; j++) {
        qwr[j] = qw[lane + 32 * j];
        kwr[j] = kw[lane + 32 * j];
    }
    float bb[4];
#pragma unroll
    for (int g = 0; g < NGROUP_; g++) bb[g] = bvec[h * NGROUP_ + g];

    const bool up16 = (lane & 16) != 0;
    const bool up8  = (lane & 8) != 0;
    const bool up4  = (lane & 4) != 0;
    const bool up2  = (lane & 2) != 0;

    for (int tt = 0; tt < TOK_PER_BLK; tt++) {
        const int s = blockIdx.x * TOK_PER_BLK + tt;

        const float* kp = g_kbuf + (size_t)s * NK_ + h * DHEAD_;
        float kd[4], kn[4];
#pragma unroll
        for (int j = 0; j < 4; j++) kd[j] = kp[lane + 32 * j];
        float kss = wsum(kd[0]*kd[0] + kd[1]*kd[1] + kd[2]*kd[2] + kd[3]*kd[3]);
        float rk = rsqrtf(kss * (1.0f / DHEAD_) + 1e-6f);
#pragma unroll
        for (int j = 0; j < 4; j++) kn[j] = kd[j] * rk * kwr[j];

        float accg = 0.f;
#pragma unroll
        for (int g = 0; g < NGROUP_; g++) {
            const float* qp = g_qbuf + (size_t)s * NQ_ + h * (NGROUP_ * DHEAD_) + g * DHEAD_;
            float qd[4], qn[4];
#pragma unroll
            for (int j = 0; j < 4; j++) qd[j] = qp[lane + 32 * j];
            float qss = wsum(qd[0]*qd[0] + qd[1]*qd[1] + qd[2]*qd[2] + qd[3]*qd[3]);
            float rq = rsqrtf(qss * (1.0f / DHEAD_) + 1e-6f);
#pragma unroll
            for (int j = 0; j < 4; j++) qn[j] = qd[j] * rq * qwr[j];

            float dt = wsum(qn[0]*kn[0] + qn[1]*kn[1] + qn[2]*kn[2] + qn[3]*kn[3]);
            float logit = dt * inv_d + 2.f * bb[g];

            float p[SINK_];
#pragma unroll
            for (int t = 0; t < SINK_; t++) {
                float4 kv = kb4[t * 32];
                p[t] = kv.x * qn[0] + kv.y * qn[1] + kv.z * qn[2] + kv.w * qn[3];
            }

            // multi-value butterfly: 16 vals/lane -> 1 val/lane
            float v8[8];
#pragma unroll
            for (int i = 0; i < 8; i++) {
                float sd  = up16 ? p[i] : p[8 + i];
                float kp2 = up16 ? p[8 + i] : p[i];
                v8[i] = kp2 + __shfl_xor_sync(0xffffffffu, sd, 16);
            }
            float v4[4];
#pragma unroll
            for (int i = 0; i < 4; i++) {
                float sd  = up8 ? v8[i] : v8[4 + i];
                float kp2 = up8 ? v8[4 + i] : v8[i];
                v4[i] = kp2 + __shfl_xor_sync(0xffffffffu, sd, 8);
            }
            float v2[2];
#pragma unroll
            for (int i = 0; i < 2; i++) {
                float sd  = up4 ? v4[i] : v4[2 + i];
                float kp2 = up4 ? v4[2 + i] : v4[i];
                v2[i] = kp2 + __shfl_xor_sync(0xffffffffu, sd, 4);
            }
            float sd1 = up2 ? v2[0] : v2[1];
            float kp1 = up2 ? v2[1] : v2[0];
            float v1 = kp1 + __shfl_xor_sync(0xffffffffu, sd1, 2);
            float S = v1 + __shfl_xor_sync(0xffffffffu, v1, 1);

            float e = __expf(S * inv_d - logit);
            float se = 0.5f * wsum(e);
            accg += 1.f / (1.f + se);
        }
        if (lane == 0) out[(size_t)h * nseq + s] = 0.25f * accg;
    }
}

// ---------------------------------------------------------------------------
// Launch
// ---------------------------------------------------------------------------
extern "C" void kernel_launch(void* const* d_in, const int* in_sizes, int n_in,
                              void* d_out, int out_size)
{
    const float* hidden = (const float*)d_in[0];
    const float* Wq     = (const float*)d_in[1];
    const float* bq     = (const float*)d_in[2];
    const float* Wk     = (const float*)d_in[3];
    const float* qw     = (const float*)d_in[4];
    const float* kw     = (const float*)d_in[5];
    const float* bvec   = (const float*)d_in[6];
    const float* kbase  = (const float*)d_in[7];

    const int nseq = in_sizes[0] / DIN_;

    cudaFuncSetAttribute(gemm_qk, cudaFuncAttributeMaxDynamicSharedMemorySize, SMEM_TOTAL);
    cudaFuncSetAttribute(epilogue_kernel, cudaFuncAttributeMaxDynamicSharedMemorySize, EPI_SMEM);

    dim3 ggrid(NTOT_ / BN, nseq / BM);   // 20 x 256
    gemm_qk<<<ggrid, GTHREADS, SMEM_TOTAL>>>(hidden, Wq, Wk, bq);

    epilogue_kernel<<<nseq / TOK_PER_BLK, 256, EPI_SMEM>>>((float*)d_out, bvec, kbase, qw, kw, nseq);
}

// round 7
// speedup vs baseline: 1.0503x; 1.0503x over previous
#include <cuda_runtime.h>
#include <cstdint>

// ---------------------------------------------------------------------------
// Problem constants
// ---------------------------------------------------------------------------
#define DIN_   2048
#define NQ_    4096
#define NK_    1024
#define NTOT_  5120
#define DHEAD_ 128
#define NHEAD_ 8
#define NGROUP_ 4
#define SINK_  16
#define SMAX_  32768

__device__ float g_qbuf[(size_t)SMAX_ * NQ_];   // 512 MB scratch
__device__ float g_kbuf[(size_t)SMAX_ * NK_];   // 128 MB scratch

// ---------------------------------------------------------------------------
// GEMM: C[S,5120] = hidden[S,2048] @ [Wq;Wk]^T (+bq on q part)
// legacy mma.sync m16n8k8 tf32 (raw fp32 bits; RMSNorm cancels the uniform
// truncation bias). 256 threads / 8 warps, warp tile 64x64,
// BM=128 BN=256 BK=64, 2-stage ring (192KB), fragment double-buffering.
// ---------------------------------------------------------------------------
#define BM 128
#define BN 256
#define BK 64
#define NSTAGE 2
#define A_SUB (128 * 128)              // one 32-float-wide A subtile: 16 KB
#define B_SUB (256 * 128)              // one 32-float-wide B subtile: 32 KB
#define SLOT_BYTES (2 * A_SUB + 2 * B_SUB)   // 96 KB  [A0 A1 B0 B1]
#define SMEM_TOTAL (NSTAGE * SLOT_BYTES)     // 192 KB

__device__ __forceinline__ uint32_t smem_to_u32(const void* p) {
    uint32_t a;
    asm("{ .reg .u64 t; cvta.to.shared.u64 t, %1; cvt.u32.u64 %0, t; }" : "=r"(a) : "l"(p));
    return a;
}

__device__ __forceinline__ void cp16s(uint32_t dst, const float* src) {
    asm volatile("cp.async.cg.shared.global [%0], [%1], 16;\n" :: "r"(dst), "l"(src));
}

__device__ __forceinline__ void ldsm_x4(uint32_t& r0, uint32_t& r1, uint32_t& r2,
                                        uint32_t& r3, uint32_t addr) {
    asm volatile("ldmatrix.sync.aligned.m8n8.x4.shared.b16 {%0,%1,%2,%3}, [%4];"
                 : "=r"(r0), "=r"(r1), "=r"(r2), "=r"(r3) : "r"(addr));
}

__device__ __forceinline__ void mma_tf32(float c[4], const uint32_t a[4],
                                         const uint32_t b0, const uint32_t b1) {
    asm volatile(
        "mma.sync.aligned.m16n8k8.row.col.f32.tf32.tf32.f32 "
        "{%0,%1,%2,%3}, {%4,%5,%6,%7}, {%8,%9}, {%0,%1,%2,%3};\n"
        : "+f"(c[0]), "+f"(c[1]), "+f"(c[2]), "+f"(c[3])
        : "r"(a[0]), "r"(a[1]), "r"(a[2]), "r"(a[3]), "r"(b0), "r"(b1));
}

// swizzled byte offset of (row, chunk); chunk = 16B unit within the 128B row
__device__ __forceinline__ uint32_t swz(int row, int chunk) {
    return (uint32_t)(row * 128 + ((chunk ^ (row & 7)) << 4));
}

__global__ void __launch_bounds__(256, 1) gemm_qk(
    const float* __restrict__ hidden, const float* __restrict__ Wq,
    const float* __restrict__ Wk, const float* __restrict__ bq)
{
    extern __shared__ char smem[];
    const uint32_t sbase = smem_to_u32(smem);
    const int tid = threadIdx.x;
    const int lane = tid & 31, wid = tid >> 5;
    const int wm = wid >> 2, wn = wid & 3;     // 2x4 warp grid, warp tile 64x64
    const int gid = lane >> 2, tig = lane & 3;

    const int n0 = blockIdx.x * BN;
    const int m0 = blockIdx.y * BM;
    const bool isq = (n0 < NQ_);
    const float* wrow = isq ? (Wq + (size_t)n0 * DIN_) : (Wk + (size_t)(n0 - NQ_) * DIN_);
    const float* arow = hidden + (size_t)m0 * DIN_;

    float acc[4][8][4];
#pragma unroll
    for (int a = 0; a < 4; a++)
#pragma unroll
        for (int b = 0; b < 8; b++)
#pragma unroll
            for (int c = 0; c < 4; c++) acc[a][b][c] = 0.f;

    // ldmatrix per-lane source rows/chunks (stage-invariant parts)
    const int arow_l   = wm * 64 + (lane & 15);                     // + tm*16
    const int achunk_l = lane >> 4;                                 // + 2*kc
    const int brow_l   = wn * 64 + (lane & 7) + ((lane & 16) >> 1); // + np*16
    const int bchunk_l = (lane >> 3) & 1;                           // + 2*kc

    auto load_stage = [&](int s) {
        const uint32_t slot = sbase + (uint32_t)(s & 1) * SLOT_BYTES;
        const int k0 = s * BK;
#pragma unroll
        for (int sub = 0; sub < 2; sub++) {
#pragma unroll
            for (int i = 0; i < 4; i++) {      // A sub: 128 rows x 8 chunks
                int id = tid + i * 256;
                int r = id >> 3, c = id & 7;
                cp16s(slot + sub * A_SUB + swz(r, c),
                      arow + (size_t)r * DIN_ + k0 + sub * 32 + c * 4);
            }
#pragma unroll
            for (int i = 0; i < 8; i++) {      // B sub: 256 rows x 8 chunks
                int id = tid + i * 256;
                int r = id >> 3, c = id & 7;
                cp16s(slot + 2 * A_SUB + sub * B_SUB + swz(r, c),
                      wrow + (size_t)r * DIN_ + k0 + sub * 32 + c * 4);
            }
        }
        asm volatile("cp.async.commit_group;\n");
    };

    load_stage(0);
    load_stage(1);

    const int NSTEPS = DIN_ / BK;  // 32
    for (int s = 0; s < NSTEPS; s++) {
        if (s < NSTEPS - 1) asm volatile("cp.async.wait_group 1;\n" ::: "memory");
        else                asm volatile("cp.async.wait_group 0;\n" ::: "memory");
        __syncthreads();

        const uint32_t slot = sbase + (uint32_t)(s & 1) * SLOT_BYTES;

        // fragment double buffer across the 8 k8-steps of this stage
        uint32_t af[2][4][4], bf[2][4][4];
        auto load_frags = [&](int kk, uint32_t a4[4][4], uint32_t b4[4][4]) {
            const int sub = kk >> 2, kc = kk & 3;
            const uint32_t abase = slot + sub * A_SUB;
            const uint32_t bbase = slot + 2 * A_SUB + sub * B_SUB;
#pragma unroll
            for (int tm = 0; tm < 4; tm++)
                ldsm_x4(a4[tm][0], a4[tm][1], a4[tm][2], a4[tm][3],
                        abase + swz(arow_l + tm * 16, 2 * kc + achunk_l));
#pragma unroll
            for (int np = 0; np < 4; np++)
                ldsm_x4(b4[np][0], b4[np][1], b4[np][2], b4[np][3],
                        bbase + swz(brow_l + np * 16, 2 * kc + bchunk_l));
        };

        load_frags(0, af[0], bf[0]);
#pragma unroll
        for (int kk = 0; kk < 8; kk++) {
            const int cur = kk & 1, nxt = cur ^ 1;
            if (kk < 7) load_frags(kk + 1, af[nxt], bf[nxt]);
#pragma unroll
            for (int tm = 0; tm < 4; tm++)
#pragma unroll
                for (int np = 0; np < 4; np++) {
                    mma_tf32(acc[tm][2 * np],     af[cur][tm], bf[cur][np][0], bf[cur][np][1]);
                    mma_tf32(acc[tm][2 * np + 1], af[cur][tm], bf[cur][np][2], bf[cur][np][3]);
                }
        }

        __syncthreads();                       // all warps done reading slot s
        if (s + 2 < NSTEPS) load_stage(s + 2); // overwrite slot (s&1)
    }

    // ---- store (+bq on q part)
    float bq0[8], bq1[8];
#pragma unroll
    for (int tn = 0; tn < 8; tn++) {
        int col = n0 + wn * 64 + tn * 8 + 2 * tig;
        bq0[tn] = isq ? __ldg(bq + col) : 0.f;
        bq1[tn] = isq ? __ldg(bq + col + 1) : 0.f;
    }
    float* obase = isq ? g_qbuf : g_kbuf;
    const int ld = isq ? NQ_ : NK_;
    const int cb = isq ? n0 : (n0 - NQ_);

#pragma unroll
    for (int tm = 0; tm < 4; tm++) {
#pragma unroll
        for (int tn = 0; tn < 8; tn++) {
            int r = m0 + wm * 64 + tm * 16 + gid;
            int c = cb + wn * 64 + tn * 8 + 2 * tig;
            float2 v0 = make_float2(acc[tm][tn][0] + bq0[tn], acc[tm][tn][1] + bq1[tn]);
            float2 v1 = make_float2(acc[tm][tn][2] + bq0[tn], acc[tm][tn][3] + bq1[tn]);
            *reinterpret_cast<float2*>(obase + (size_t)r * ld + c) = v0;
            *reinterpret_cast<float2*>(obase + (size_t)(r + 8) * ld + c) = v1;
        }
    }
}

// ---------------------------------------------------------------------------
// Epilogue (R4 version — best measured): RMSNorm(q), RMSNorm(k), logits,
// sink gate, mean over groups; k_base in registers, butterfly reductions.
// ---------------------------------------------------------------------------
#define TOK_PER_BLK 16

__device__ __forceinline__ float wsum(float v) {
    v += __shfl_xor_sync(0xffffffffu, v, 16);
    v += __shfl_xor_sync(0xffffffffu, v, 8);
    v += __shfl_xor_sync(0xffffffffu, v, 4);
    v += __shfl_xor_sync(0xffffffffu, v, 2);
    v += __shfl_xor_sync(0xffffffffu, v, 1);
    return v;
}

__global__ void __launch_bounds__(256) epilogue_kernel(
    float* __restrict__ out, const float* __restrict__ bvec,
    const float* __restrict__ k_base, const float* __restrict__ qw,
    const float* __restrict__ kw, int nseq)
{
    const int lane = threadIdx.x & 31;
    const int h = threadIdx.x >> 5;
    const float inv_d = 0.08838834764831845f;

    float kb[SINK_][4];
#pragma unroll
    for (int t = 0; t < SINK_; t++)
#pragma unroll
        for (int j = 0; j < 4; j++)
            kb[t][j] = k_base[(size_t)(h * SINK_ + t) * DHEAD_ + lane + 32 * j];

    float qwr[4], kwr[4];
#pragma unroll
    for (int j = 0; j < 4; j++) {
        qwr[j] = qw[lane + 32 * j];
        kwr[j] = kw[lane + 32 * j];
    }
    float bb[4];
#pragma unroll
    for (int g = 0; g < NGROUP_; g++) bb[g] = bvec[h * NGROUP_ + g];

    const bool up16 = (lane & 16) != 0;
    const bool up8  = (lane & 8) != 0;
    const bool up4  = (lane & 4) != 0;
    const bool up2  = (lane & 2) != 0;

    for (int tt = 0; tt < TOK_PER_BLK; tt++) {
        const int s = blockIdx.x * TOK_PER_BLK + tt;

        const float* kp = g_kbuf + (size_t)s * NK_ + h * DHEAD_;
        float kd[4], kn[4];
#pragma unroll
        for (int j = 0; j < 4; j++) kd[j] = kp[lane + 32 * j];
        float kss = wsum(kd[0]*kd[0] + kd[1]*kd[1] + kd[2]*kd[2] + kd[3]*kd[3]);
        float rk = rsqrtf(kss * (1.0f / DHEAD_) + 1e-6f);
#pragma unroll
        for (int j = 0; j < 4; j++) kn[j] = kd[j] * rk * kwr[j];

        float accg = 0.f;
#pragma unroll
        for (int g = 0; g < NGROUP_; g++) {
            const float* qp = g_qbuf + (size_t)s * NQ_ + h * (NGROUP_ * DHEAD_) + g * DHEAD_;
            float qd[4], qn[4];
#pragma unroll
            for (int j = 0; j < 4; j++) qd[j] = qp[lane + 32 * j];
            float qss = wsum(qd[0]*qd[0] + qd[1]*qd[1] + qd[2]*qd[2] + qd[3]*qd[3]);
            float rq = rsqrtf(qss * (1.0f / DHEAD_) + 1e-6f);
#pragma unroll
            for (int j = 0; j < 4; j++) qn[j] = qd[j] * rq * qwr[j];

            float dt = wsum(qn[0]*kn[0] + qn[1]*kn[1] + qn[2]*kn[2] + qn[3]*kn[3]);
            float logit = dt * inv_d + 2.f * bb[g];

            float p[SINK_];
#pragma unroll
            for (int t = 0; t < SINK_; t++)
                p[t] = kb[t][0]*qn[0] + kb[t][1]*qn[1] + kb[t][2]*qn[2] + kb[t][3]*qn[3];

            // multi-value butterfly: 16 vals/lane -> 1 val/lane
            float v8[8];
#pragma unroll
            for (int i = 0; i < 8; i++) {
                float sd  = up16 ? p[i] : p[8 + i];
                float kp2 = up16 ? p[8 + i] : p[i];
                v8[i] = kp2 + __shfl_xor_sync(0xffffffffu, sd, 16);
            }
            float v4[4];
#pragma unroll
            for (int i = 0; i < 4; i++) {
                float sd  = up8 ? v8[i] : v8[4 + i];
                float kp2 = up8 ? v8[4 + i] : v8[i];
                v4[i] = kp2 + __shfl_xor_sync(0xffffffffu, sd, 8);
            }
            float v2[2];
#pragma unroll
            for (int i = 0; i < 2; i++) {
                float sd  = up4 ? v4[i] : v4[2 + i];
                float kp2 = up4 ? v4[2 + i] : v4[i];
                v2[i] = kp2 + __shfl_xor_sync(0xffffffffu, sd, 4);
            }
            float sd1 = up2 ? v2[0] : v2[1];
            float kp1 = up2 ? v2[1] : v2[0];
            float v1 = kp1 + __shfl_xor_sync(0xffffffffu, sd1, 2);
            float S = v1 + __shfl_xor_sync(0xffffffffu, v1, 1);

            float e = __expf(S * inv_d - logit);
            float se = 0.5f * wsum(e);
            accg += 1.f / (1.f + se);
        }
        if (lane == 0) out[(size_t)h * nseq + s] = 0.25f * accg;
    }
}

// ---------------------------------------------------------------------------
// Launch
// ---------------------------------------------------------------------------
extern "C" void kernel_launch(void* const* d_in, const int* in_sizes, int n_in,
                              void* d_out, int out_size)
{
    const float* hidden = (const float*)d_in[0];
    const float* Wq     = (const float*)d_in[1];
    const float* bq     = (const float*)d_in[2];
    const float* Wk     = (const float*)d_in[3];
    const float* qw     = (const float*)d_in[4];
    const float* kw     = (const float*)d_in[5];
    const float* bvec   = (const float*)d_in[6];
    const float* kbase  = (const float*)d_in[7];

    const int nseq = in_sizes[0] / DIN_;

    cudaFuncSetAttribute(gemm_qk, cudaFuncAttributeMaxDynamicSharedMemorySize, SMEM_TOTAL);

    dim3 ggrid(NTOT_ / BN, nseq / BM);   // 20 x 256
    gemm_qk<<<ggrid, 256, SMEM_TOTAL>>>(hidden, Wq, Wk, bq);

    epilogue_kernel<<<nseq / TOK_PER_BLK, 256>>>((float*)d_out, bvec, kbase, qw, kw, nseq);
}

// round 8
// speedup vs baseline: 1.7530x; 1.6690x over previous
#include <cuda_runtime.h>
#include <cuda_fp16.h>
#include <cstdint>

// ---------------------------------------------------------------------------
// Problem constants
// ---------------------------------------------------------------------------
#define DIN_   2048
#define NQ_    4096
#define NK_    1024
#define NTOT_  5120
#define DHEAD_ 128
#define NHEAD_ 8
#define NGROUP_ 4
#define SINK_  16
#define SMAX_  32768

__device__ float  g_qbuf[(size_t)SMAX_ * NQ_];    // 512 MB f32 scratch
__device__ float  g_kbuf[(size_t)SMAX_ * NK_];    // 128 MB f32 scratch
__device__ __half g_hbuf[(size_t)SMAX_ * DIN_];   // 128 MB fp16 hidden
__device__ __half g_wbuf[(size_t)NTOT_ * DIN_];   // 20 MB  fp16 [Wq;Wk]

// ---------------------------------------------------------------------------
// fp32 -> fp16 conversion (RN), vectorized
// ---------------------------------------------------------------------------
__global__ void __launch_bounds__(256) cvt_fp16(const float4* __restrict__ src,
                                                uint2* __restrict__ dst, int n4)
{
    int i = blockIdx.x * blockDim.x + threadIdx.x;
    if (i < n4) {
        float4 v = src[i];
        __half2 h0 = __floats2half2_rn(v.x, v.y);
        __half2 h1 = __floats2half2_rn(v.z, v.w);
        uint2 o;
        o.x = *reinterpret_cast<uint32_t*>(&h0);
        o.y = *reinterpret_cast<uint32_t*>(&h1);
        dst[i] = o;
    }
}

// ---------------------------------------------------------------------------
// GEMM: C[S,5120] = hidden[S,2048] @ [Wq;Wk]^T (+bq on q part)
// legacy mma.sync m16n8k16 fp16 (f32 accum), ldmatrix frags,
// BM=128 BN=256 BK=64(fp16), 3-stage cp.async ring (144 KB)
// ---------------------------------------------------------------------------
#define BM 128
#define BN 256
#define BK 64                           // fp16 elements per stage
#define NSTAGE 3
#define A_BYTES (128 * 128)             // 128 rows x 64 fp16 (128B)
#define B_BYTES (256 * 128)             // 256 rows x 64 fp16
#define SLOT_BYTES (A_BYTES + B_BYTES)  // 48 KB
#define SMEM_TOTAL (NSTAGE * SLOT_BYTES)   // 144 KB

__device__ __forceinline__ uint32_t smem_to_u32(const void* p) {
    uint32_t a;
    asm("{ .reg .u64 t; cvta.to.shared.u64 t, %1; cvt.u32.u64 %0, t; }" : "=r"(a) : "l"(p));
    return a;
}

__device__ __forceinline__ void cp16s(uint32_t dst, const __half* src) {
    asm volatile("cp.async.cg.shared.global [%0], [%1], 16;\n" :: "r"(dst), "l"(src));
}

__device__ __forceinline__ void ldsm_x4(uint32_t& r0, uint32_t& r1, uint32_t& r2,
                                        uint32_t& r3, uint32_t addr) {
    asm volatile("ldmatrix.sync.aligned.m8n8.x4.shared.b16 {%0,%1,%2,%3}, [%4];"
                 : "=r"(r0), "=r"(r1), "=r"(r2), "=r"(r3) : "r"(addr));
}

__device__ __forceinline__ void mma_f16(float c[4], const uint32_t a[4],
                                        const uint32_t b0, const uint32_t b1) {
    asm volatile(
        "mma.sync.aligned.m16n8k16.row.col.f32.f16.f16.f32 "
        "{%0,%1,%2,%3}, {%4,%5,%6,%7}, {%8,%9}, {%0,%1,%2,%3};\n"
        : "+f"(c[0]), "+f"(c[1]), "+f"(c[2]), "+f"(c[3])
        : "r"(a[0]), "r"(a[1]), "r"(a[2]), "r"(a[3]), "r"(b0), "r"(b1));
}

// swizzled byte offset of (row, chunk); chunk = 16B unit within the 128B row
__device__ __forceinline__ uint32_t swz(int row, int chunk) {
    return (uint32_t)(row * 128 + ((chunk ^ (row & 7)) << 4));
}

__global__ void __launch_bounds__(256, 1) gemm_qk(const float* __restrict__ bq)
{
    extern __shared__ char smem[];
    const uint32_t sbase = smem_to_u32(smem);
    const int tid = threadIdx.x;
    const int lane = tid & 31, wid = tid >> 5;
    const int wm = wid >> 2, wn = wid & 3;     // 2x4 warp grid, warp tile 64x64
    const int gid = lane >> 2, tig = lane & 3;

    const int n0 = blockIdx.x * BN;
    const int m0 = blockIdx.y * BM;
    const bool isq = (n0 < NQ_);
    const __half* wrow = g_wbuf + (size_t)n0 * DIN_;
    const __half* arow = g_hbuf + (size_t)m0 * DIN_;

    float acc[4][8][4];
#pragma unroll
    for (int a = 0; a < 4; a++)
#pragma unroll
        for (int b = 0; b < 8; b++)
#pragma unroll
            for (int c = 0; c < 4; c++) acc[a][b][c] = 0.f;

    // ldmatrix per-lane source rows/chunks (stage-invariant parts)
    // A x4 -> m16k16 frag: rows (lane&15), chunk 2ks + (lane>>4)
    const int arow_l   = wm * 64 + (lane & 15);                     // + tm*16
    const int achunk_l = lane >> 4;                                 // + 2*ks
    // B x4 -> two n8 B-frags: rows wn*64+np*16+{0-7|8-15}, chunk 2ks+{0,1}
    const int brow_l   = wn * 64 + (lane & 7) + ((lane & 16) >> 1); // + np*16
    const int bchunk_l = (lane >> 3) & 1;                           // + 2*ks

    auto load_stage = [&](int s) {
        const uint32_t slot = sbase + (uint32_t)(s % NSTAGE) * SLOT_BYTES;
        const int k0 = s * BK;
#pragma unroll
        for (int i = 0; i < 4; i++) {          // A: 128 rows x 8 chunks = 1024
            int id = tid + i * 256;
            int r = id >> 3, c = id & 7;
            cp16s(slot + swz(r, c), arow + (size_t)r * DIN_ + k0 + c * 8);
        }
#pragma unroll
        for (int i = 0; i < 8; i++) {          // B: 256 rows x 8 chunks = 2048
            int id = tid + i * 256;
            int r = id >> 3, c = id & 7;
            cp16s(slot + A_BYTES + swz(r, c), wrow + (size_t)r * DIN_ + k0 + c * 8);
        }
        asm volatile("cp.async.commit_group;\n");
    };

    load_stage(0);
    load_stage(1);

    const int NSTEPS = DIN_ / BK;  // 32
    for (int s = 0; s < NSTEPS; s++) {
        if (s < NSTEPS - 1) asm volatile("cp.async.wait_group 1;\n" ::: "memory");
        else                asm volatile("cp.async.wait_group 0;\n" ::: "memory");
        __syncthreads();

        const uint32_t slot = sbase + (uint32_t)(s % NSTAGE) * SLOT_BYTES;
#pragma unroll
        for (int ks = 0; ks < 4; ks++) {       // 4 x k16 per stage
            uint32_t af[4][4], bf[4][4];
#pragma unroll
            for (int tm = 0; tm < 4; tm++)
                ldsm_x4(af[tm][0], af[tm][1], af[tm][2], af[tm][3],
                        slot + swz(arow_l + tm * 16, 2 * ks + achunk_l));
#pragma unroll
            for (int np = 0; np < 4; np++)
                ldsm_x4(bf[np][0], bf[np][1], bf[np][2], bf[np][3],
                        slot + A_BYTES + swz(brow_l + np * 16, 2 * ks + bchunk_l));
#pragma unroll
            for (int tm = 0; tm < 4; tm++)
#pragma unroll
                for (int np = 0; np < 4; np++) {
                    mma_f16(acc[tm][2 * np],     af[tm], bf[np][0], bf[np][1]);
                    mma_f16(acc[tm][2 * np + 1], af[tm], bf[np][2], bf[np][3]);
                }
        }

        if (s + 2 < NSTEPS) load_stage(s + 2);
    }

    // ---- store (+bq on q part)
    float bq0[8], bq1[8];
#pragma unroll
    for (int tn = 0; tn < 8; tn++) {
        int col = n0 + wn * 64 + tn * 8 + 2 * tig;
        bq0[tn] = isq ? __ldg(bq + col) : 0.f;
        bq1[tn] = isq ? __ldg(bq + col + 1) : 0.f;
    }
    float* obase = isq ? g_qbuf : g_kbuf;
    const int ld = isq ? NQ_ : NK_;
    const int cb = isq ? n0 : (n0 - NQ_);

#pragma unroll
    for (int tm = 0; tm < 4; tm++) {
#pragma unroll
        for (int tn = 0; tn < 8; tn++) {
            int r = m0 + wm * 64 + tm * 16 + gid;
            int c = cb + wn * 64 + tn * 8 + 2 * tig;
            float2 v0 = make_float2(acc[tm][tn][0] + bq0[tn], acc[tm][tn][1] + bq1[tn]);
            float2 v1 = make_float2(acc[tm][tn][2] + bq0[tn], acc[tm][tn][3] + bq1[tn]);
            *reinterpret_cast<float2*>(obase + (size_t)r * ld + c) = v0;
            *reinterpret_cast<float2*>(obase + (size_t)(r + 8) * ld + c) = v1;
        }
    }
}

// ---------------------------------------------------------------------------
// Epilogue (best measured R4 version): RMSNorm(q), RMSNorm(k), logits,
// sink gate, mean over groups; k_base in registers, butterfly reductions.
// ---------------------------------------------------------------------------
#define TOK_PER_BLK 16

__device__ __forceinline__ float wsum(float v) {
    v += __shfl_xor_sync(0xffffffffu, v, 16);
    v += __shfl_xor_sync(0xffffffffu, v, 8);
    v += __shfl_xor_sync(0xffffffffu, v, 4);
    v += __shfl_xor_sync(0xffffffffu, v, 2);
    v += __shfl_xor_sync(0xffffffffu, v, 1);
    return v;
}

__global__ void __launch_bounds__(256) epilogue_kernel(
    float* __restrict__ out, const float* __restrict__ bvec,
    const float* __restrict__ k_base, const float* __restrict__ qw,
    const float* __restrict__ kw, int nseq)
{
    const int lane = threadIdx.x & 31;
    const int h = threadIdx.x >> 5;
    const float inv_d = 0.08838834764831845f;

    float kb[SINK_][4];
#pragma unroll
    for (int t = 0; t < SINK_; t++)
#pragma unroll
        for (int j = 0; j < 4; j++)
            kb[t][j] = k_base[(size_t)(h * SINK_ + t) * DHEAD_ + lane + 32 * j];

    float qwr[4], kwr[4];
#pragma unroll
    for (int j = 0; j < 4; j++) {
        qwr[j] = qw[lane + 32 * j];
        kwr[j] = kw[lane + 32 * j];
    }
    float bb[4];
#pragma unroll
    for (int g = 0; g < NGROUP_; g++) bb[g] = bvec[h * NGROUP_ + g];

    const bool up16 = (lane & 16) != 0;
    const bool up8  = (lane & 8) != 0;
    const bool up4  = (lane & 4) != 0;
    const bool up2  = (lane & 2) != 0;

    for (int tt = 0; tt < TOK_PER_BLK; tt++) {
        const int s = blockIdx.x * TOK_PER_BLK + tt;

        const float* kp = g_kbuf + (size_t)s * NK_ + h * DHEAD_;
        float kd[4], kn[4];
#pragma unroll
        for (int j = 0; j < 4; j++) kd[j] = kp[lane + 32 * j];
        float kss = wsum(kd[0]*kd[0] + kd[1]*kd[1] + kd[2]*kd[2] + kd[3]*kd[3]);
        float rk = rsqrtf(kss * (1.0f / DHEAD_) + 1e-6f);
#pragma unroll
        for (int j = 0; j < 4; j++) kn[j] = kd[j] * rk * kwr[j];

        float accg = 0.f;
#pragma unroll
        for (int g = 0; g < NGROUP_; g++) {
            const float* qp = g_qbuf + (size_t)s * NQ_ + h * (NGROUP_ * DHEAD_) + g * DHEAD_;
            float qd[4], qn[4];
#pragma unroll
            for (int j = 0; j < 4; j++) qd[j] = qp[lane + 32 * j];
            float qss = wsum(qd[0]*qd[0] + qd[1]*qd[1] + qd[2]*qd[2] + qd[3]*qd[3]);
            float rq = rsqrtf(qss * (1.0f / DHEAD_) + 1e-6f);
#pragma unroll
            for (int j = 0; j < 4; j++) qn[j] = qd[j] * rq * qwr[j];

            float dt = wsum(qn[0]*kn[0] + qn[1]*kn[1] + qn[2]*kn[2] + qn[3]*kn[3]);
            float logit = dt * inv_d + 2.f * bb[g];

            float p[SINK_];
#pragma unroll
            for (int t = 0; t < SINK_; t++)
                p[t] = kb[t][0]*qn[0] + kb[t][1]*qn[1] + kb[t][2]*qn[2] + kb[t][3]*qn[3];

            // multi-value butterfly: 16 vals/lane -> 1 val/lane
            float v8[8];
#pragma unroll
            for (int i = 0; i < 8; i++) {
                float sd  = up16 ? p[i] : p[8 + i];
                float kp2 = up16 ? p[8 + i] : p[i];
                v8[i] = kp2 + __shfl_xor_sync(0xffffffffu, sd, 16);
            }
            float v4[4];
#pragma unroll
            for (int i = 0; i < 4; i++) {
                float sd  = up8 ? v8[i] : v8[4 + i];
                float kp2 = up8 ? v8[4 + i] : v8[i];
                v4[i] = kp2 + __shfl_xor_sync(0xffffffffu, sd, 8);
            }
            float v2[2];
#pragma unroll
            for (int i = 0; i < 2; i++) {
                float sd  = up4 ? v4[i] : v4[2 + i];
                float kp2 = up4 ? v4[2 + i] : v4[i];
                v2[i] = kp2 + __shfl_xor_sync(0xffffffffu, sd, 4);
            }
            float sd1 = up2 ? v2[0] : v2[1];
            float kp1 = up2 ? v2[1] : v2[0];
            float v1 = kp1 + __shfl_xor_sync(0xffffffffu, sd1, 2);
            float S = v1 + __shfl_xor_sync(0xffffffffu, v1, 1);

            float e = __expf(S * inv_d - logit);
            float se = 0.5f * wsum(e);
            accg += 1.f / (1.f + se);
        }
        if (lane == 0) out[(size_t)h * nseq + s] = 0.25f * accg;
    }
}

// ---------------------------------------------------------------------------
// Launch
// ---------------------------------------------------------------------------
extern "C" void kernel_launch(void* const* d_in, const int* in_sizes, int n_in,
                              void* d_out, int out_size)
{
    const float* hidden = (const float*)d_in[0];
    const float* Wq     = (const float*)d_in[1];
    const float* bq     = (const float*)d_in[2];
    const float* Wk     = (const float*)d_in[3];
    const float* qw     = (const float*)d_in[4];
    const float* kw     = (const float*)d_in[5];
    const float* bvec   = (const float*)d_in[6];
    const float* kbase  = (const float*)d_in[7];

    const int nseq = in_sizes[0] / DIN_;

    __half* hb;  cudaGetSymbolAddress((void**)&hb, g_hbuf);
    __half* wb;  cudaGetSymbolAddress((void**)&wb, g_wbuf);

    // fp32 -> fp16 conversions
    {
        int n4 = nseq * DIN_ / 4;
        cvt_fp16<<<(n4 + 255) / 256, 256>>>((const float4*)hidden, (uint2*)hb, n4);
        n4 = NQ_ * DIN_ / 4;
        cvt_fp16<<<(n4 + 255) / 256, 256>>>((const float4*)Wq, (uint2*)wb, n4);
        n4 = NK_ * DIN_ / 4;
        cvt_fp16<<<(n4 + 255) / 256, 256>>>((const float4*)Wk,
                                            (uint2*)(wb + (size_t)NQ_ * DIN_), n4);
    }

    cudaFuncSetAttribute(gemm_qk, cudaFuncAttributeMaxDynamicSharedMemorySize, SMEM_TOTAL);

    dim3 ggrid(NTOT_ / BN, nseq / BM);   // 20 x 256
    gemm_qk<<<ggrid, 256, SMEM_TOTAL>>>(bq);

    epilogue_kernel<<<nseq / TOK_PER_BLK, 256>>>((float*)d_out, bvec, kbase, qw, kw, nseq);
}

// round 9
// speedup vs baseline: 1.7840x; 1.0177x over previous
#include <cuda_runtime.h>
#include <cuda_fp16.h>
#include <cstdint>

// ---------------------------------------------------------------------------
// Problem constants
// ---------------------------------------------------------------------------
#define DIN_   2048
#define NQ_    4096
#define NK_    1024
#define NTOT_  5120
#define DHEAD_ 128
#define NHEAD_ 8
#define NGROUP_ 4
#define SINK_  16
#define SMAX_  32768

__device__ __half g_qh[(size_t)SMAX_ * NQ_];     // 256 MB fp16 q scratch
__device__ __half g_kh[(size_t)SMAX_ * NK_];     // 64 MB  fp16 k scratch
__device__ __half g_hbuf[(size_t)SMAX_ * DIN_];  // 128 MB fp16 hidden
__device__ __half g_wbuf[(size_t)NTOT_ * DIN_];  // 20 MB  fp16 [Wq;Wk]

// ---------------------------------------------------------------------------
// fp32 -> fp16 conversion (RN), vectorized
// ---------------------------------------------------------------------------
__global__ void __launch_bounds__(256) cvt_fp16(const float4* __restrict__ src,
                                                uint2* __restrict__ dst, int n4)
{
    int i = blockIdx.x * blockDim.x + threadIdx.x;
    if (i < n4) {
        float4 v = src[i];
        __half2 h0 = __floats2half2_rn(v.x, v.y);
        __half2 h1 = __floats2half2_rn(v.z, v.w);
        uint2 o;
        o.x = *reinterpret_cast<uint32_t*>(&h0);
        o.y = *reinterpret_cast<uint32_t*>(&h1);
        dst[i] = o;
    }
}

// ---------------------------------------------------------------------------
// GEMM: C[S,5120] = hidden[S,2048] @ [Wq;Wk]^T (+bq on q part), fp16 in/out
// legacy mma.sync m16n8k16 (f32 accum), ldmatrix frags,
// BM=128 BN=256 BK=64(fp16), 3-stage cp.async ring (144 KB)
// ---------------------------------------------------------------------------
#define BM 128
#define BN 256
#define BK 64
#define NSTAGE 3
#define A_BYTES (128 * 128)
#define B_BYTES (256 * 128)
#define SLOT_BYTES (A_BYTES + B_BYTES)
#define SMEM_TOTAL (NSTAGE * SLOT_BYTES)   // 144 KB

__device__ __forceinline__ uint32_t smem_to_u32(const void* p) {
    uint32_t a;
    asm("{ .reg .u64 t; cvta.to.shared.u64 t, %1; cvt.u32.u64 %0, t; }" : "=r"(a) : "l"(p));
    return a;
}

__device__ __forceinline__ void cp16s(uint32_t dst, const __half* src) {
    asm volatile("cp.async.cg.shared.global [%0], [%1], 16;\n" :: "r"(dst), "l"(src));
}

__device__ __forceinline__ void ldsm_x4(uint32_t& r0, uint32_t& r1, uint32_t& r2,
                                        uint32_t& r3, uint32_t addr) {
    asm volatile("ldmatrix.sync.aligned.m8n8.x4.shared.b16 {%0,%1,%2,%3}, [%4];"
                 : "=r"(r0), "=r"(r1), "=r"(r2), "=r"(r3) : "r"(addr));
}

__device__ __forceinline__ void mma_f16(float c[4], const uint32_t a[4],
                                        const uint32_t b0, const uint32_t b1) {
    asm volatile(
        "mma.sync.aligned.m16n8k16.row.col.f32.f16.f16.f32 "
        "{%0,%1,%2,%3}, {%4,%5,%6,%7}, {%8,%9}, {%0,%1,%2,%3};\n"
        : "+f"(c[0]), "+f"(c[1]), "+f"(c[2]), "+f"(c[3])
        : "r"(a[0]), "r"(a[1]), "r"(a[2]), "r"(a[3]), "r"(b0), "r"(b1));
}

__device__ __forceinline__ uint32_t swz(int row, int chunk) {
    return (uint32_t)(row * 128 + ((chunk ^ (row & 7)) << 4));
}

__global__ void __launch_bounds__(256, 1) gemm_qk(const float* __restrict__ bq)
{
    extern __shared__ char smem[];
    const uint32_t sbase = smem_to_u32(smem);
    const int tid = threadIdx.x;
    const int lane = tid & 31, wid = tid >> 5;
    const int wm = wid >> 2, wn = wid & 3;
    const int gid = lane >> 2, tig = lane & 3;

    const int n0 = blockIdx.x * BN;
    const int m0 = blockIdx.y * BM;
    const bool isq = (n0 < NQ_);
    const __half* wrow = g_wbuf + (size_t)n0 * DIN_;
    const __half* arow = g_hbuf + (size_t)m0 * DIN_;

    float acc[4][8][4];
#pragma unroll
    for (int a = 0; a < 4; a++)
#pragma unroll
        for (int b = 0; b < 8; b++)
#pragma unroll
            for (int c = 0; c < 4; c++) acc[a][b][c] = 0.f;

    const int arow_l   = wm * 64 + (lane & 15);
    const int achunk_l = lane >> 4;
    const int brow_l   = wn * 64 + (lane & 7) + ((lane & 16) >> 1);
    const int bchunk_l = (lane >> 3) & 1;

    auto load_stage = [&](int s) {
        const uint32_t slot = sbase + (uint32_t)(s % NSTAGE) * SLOT_BYTES;
        const int k0 = s * BK;
#pragma unroll
        for (int i = 0; i < 4; i++) {
            int id = tid + i * 256;
            int r = id >> 3, c = id & 7;
            cp16s(slot + swz(r, c), arow + (size_t)r * DIN_ + k0 + c * 8);
        }
#pragma unroll
        for (int i = 0; i < 8; i++) {
            int id = tid + i * 256;
            int r = id >> 3, c = id & 7;
            cp16s(slot + A_BYTES + swz(r, c), wrow + (size_t)r * DIN_ + k0 + c * 8);
        }
        asm volatile("cp.async.commit_group;\n");
    };

    load_stage(0);
    load_stage(1);

    const int NSTEPS = DIN_ / BK;  // 32
    for (int s = 0; s < NSTEPS; s++) {
        if (s < NSTEPS - 1) asm volatile("cp.async.wait_group 1;\n" ::: "memory");
        else                asm volatile("cp.async.wait_group 0;\n" ::: "memory");
        __syncthreads();

        const uint32_t slot = sbase + (uint32_t)(s % NSTAGE) * SLOT_BYTES;
#pragma unroll
        for (int ks = 0; ks < 4; ks++) {
            uint32_t af[4][4], bf[4][4];
#pragma unroll
            for (int tm = 0; tm < 4; tm++)
                ldsm_x4(af[tm][0], af[tm][1], af[tm][2], af[tm][3],
                        slot + swz(arow_l + tm * 16, 2 * ks + achunk_l));
#pragma unroll
            for (int np = 0; np < 4; np++)
                ldsm_x4(bf[np][0], bf[np][1], bf[np][2], bf[np][3],
                        slot + A_BYTES + swz(brow_l + np * 16, 2 * ks + bchunk_l));
#pragma unroll
            for (int tm = 0; tm < 4; tm++)
#pragma unroll
                for (int np = 0; np < 4; np++) {
                    mma_f16(acc[tm][2 * np],     af[tm], bf[np][0], bf[np][1]);
                    mma_f16(acc[tm][2 * np + 1], af[tm], bf[np][2], bf[np][3]);
                }
        }

        if (s + 2 < NSTEPS) load_stage(s + 2);
    }

    // ---- store fp16 (+bq on q part)
    float bq0[8], bq1[8];
#pragma unroll
    for (int tn = 0; tn < 8; tn++) {
        int col = n0 + wn * 64 + tn * 8 + 2 * tig;
        bq0[tn] = isq ? __ldg(bq + col) : 0.f;
        bq1[tn] = isq ? __ldg(bq + col + 1) : 0.f;
    }
    __half* obase = isq ? g_qh : g_kh;
    const int ld = isq ? NQ_ : NK_;
    const int cb = isq ? n0 : (n0 - NQ_);

#pragma unroll
    for (int tm = 0; tm < 4; tm++) {
#pragma unroll
        for (int tn = 0; tn < 8; tn++) {
            int r = m0 + wm * 64 + tm * 16 + gid;
            int c = cb + wn * 64 + tn * 8 + 2 * tig;
            __half2 v0 = __floats2half2_rn(acc[tm][tn][0] + bq0[tn], acc[tm][tn][1] + bq1[tn]);
            __half2 v1 = __floats2half2_rn(acc[tm][tn][2] + bq0[tn], acc[tm][tn][3] + bq1[tn]);
            *reinterpret_cast<__half2*>(obase + (size_t)r * ld + c) = v0;
            *reinterpret_cast<__half2*>(obase + (size_t)(r + 8) * ld + c) = v1;
        }
    }
}

// ---------------------------------------------------------------------------
// Epilogue: fp16 scratch reads; rq/rk folded OUT of the reductions so qss,
// dtt and the 16 sink partials reduce concurrently (short critical path).
// Lane owns dims d = 4*lane + j (j=0..3).
// ---------------------------------------------------------------------------
#define TOK_PER_BLK 16

__device__ __forceinline__ float wsum(float v) {
    v += __shfl_xor_sync(0xffffffffu, v, 16);
    v += __shfl_xor_sync(0xffffffffu, v, 8);
    v += __shfl_xor_sync(0xffffffffu, v, 4);
    v += __shfl_xor_sync(0xffffffffu, v, 2);
    v += __shfl_xor_sync(0xffffffffu, v, 1);
    return v;
}

__device__ __forceinline__ void ld4h(float o[4], const __half* p) {
    uint2 r = *reinterpret_cast<const uint2*>(p);
    __half2 h0 = *reinterpret_cast<__half2*>(&r.x);
    __half2 h1 = *reinterpret_cast<__half2*>(&r.y);
    float2 f0 = __half22float2(h0), f1 = __half22float2(h1);
    o[0] = f0.x; o[1] = f0.y; o[2] = f1.x; o[3] = f1.y;
}

__global__ void __launch_bounds__(256) epilogue_kernel(
    float* __restrict__ out, const float* __restrict__ bvec,
    const float* __restrict__ k_base, const float* __restrict__ qw,
    const float* __restrict__ kw, int nseq)
{
    const int lane = threadIdx.x & 31;
    const int h = threadIdx.x >> 5;
    const float inv_d = 0.08838834764831845f;

    // per-lane dims d = 4*lane + j
    float qwr[4], kwr[4];
#pragma unroll
    for (int j = 0; j < 4; j++) {
        qwr[j] = qw[4 * lane + j];
        kwr[j] = kw[4 * lane + j];
    }
    // kbq[t][j] = k_base[h,t,d] * qw[d]  (qw folded in)
    float kbq[SINK_][4];
#pragma unroll
    for (int t = 0; t < SINK_; t++)
#pragma unroll
        for (int j = 0; j < 4; j++)
            kbq[t][j] = k_base[(size_t)(h * SINK_ + t) * DHEAD_ + 4 * lane + j] * qwr[j];

    float bb[4];
#pragma unroll
    for (int g = 0; g < NGROUP_; g++) bb[g] = bvec[h * NGROUP_ + g];

    const bool up16 = (lane & 16) != 0;
    const bool up8  = (lane & 8) != 0;
    const bool up4  = (lane & 4) != 0;
    const bool up2  = (lane & 2) != 0;

    for (int tt = 0; tt < TOK_PER_BLK; tt++) {
        const int s = blockIdx.x * TOK_PER_BLK + tt;

        // ---- k row: raw loads; rk folded out of reductions
        float kd[4];
        ld4h(kd, g_kh + (size_t)s * NK_ + h * DHEAD_ + 4 * lane);
        float kss_p = kd[0]*kd[0] + kd[1]*kd[1] + kd[2]*kd[2] + kd[3]*kd[3];
        float kdq[4];   // kd * kw * qw  (for the k.q dot)
#pragma unroll
        for (int j = 0; j < 4; j++) kdq[j] = kd[j] * kwr[j] * qwr[j];
        float kss = wsum(kss_p);
        float rk = rsqrtf(kss * (1.0f / DHEAD_) + 1e-6f);

        float accg = 0.f;
#pragma unroll
        for (int g = 0; g < NGROUP_; g++) {
            float qd[4];
            ld4h(qd, g_qh + (size_t)s * NQ_ + h * (NGROUP_ * DHEAD_) + g * DHEAD_ + 4 * lane);

            // three INDEPENDENT reductions: qss, dtt, p[16]
            float qss_p = qd[0]*qd[0] + qd[1]*qd[1] + qd[2]*qd[2] + qd[3]*qd[3];
            float dtt_p = kdq[0]*qd[0] + kdq[1]*qd[1] + kdq[2]*qd[2] + kdq[3]*qd[3];
            float p[SINK_];
#pragma unroll
            for (int t = 0; t < SINK_; t++)
                p[t] = kbq[t][0]*qd[0] + kbq[t][1]*qd[1] + kbq[t][2]*qd[2] + kbq[t][3]*qd[3];

            float qss = wsum(qss_p);
            float dtt = wsum(dtt_p);

            // multi-value butterfly: 16 vals/lane -> 1 val/lane (t=(lane>>1)&15)
            float v8[8];
#pragma unroll
            for (int i = 0; i < 8; i++) {
                float sd  = up16 ? p[i] : p[8 + i];
                float kp2 = up16 ? p[8 + i] : p[i];
                v8[i] = kp2 + __shfl_xor_sync(0xffffffffu, sd, 16);
            }
            float v4[4];
#pragma unroll
            for (int i = 0; i < 4; i++) {
                float sd  = up8 ? v8[i] : v8[4 + i];
                float kp2 = up8 ? v8[4 + i] : v8[i];
                v4[i] = kp2 + __shfl_xor_sync(0xffffffffu, sd, 8);
            }
            float v2[2];
#pragma unroll
            for (int i = 0; i < 2; i++) {
                float sd  = up4 ? v4[i] : v4[2 + i];
                float kp2 = up4 ? v4[2 + i] : v4[i];
                v2[i] = kp2 + __shfl_xor_sync(0xffffffffu, sd, 4);
            }
            float sd1 = up2 ? v2[0] : v2[1];
            float kp1 = up2 ? v2[1] : v2[0];
            float v1 = kp1 + __shfl_xor_sync(0xffffffffu, sd1, 2);
            float S = v1 + __shfl_xor_sync(0xffffffffu, v1, 1);

            float rq = rsqrtf(qss * (1.0f / DHEAD_) + 1e-6f);
            float logit = rk * rq * dtt * inv_d + 2.f * bb[g];

            float e = __expf(rq * S * inv_d - logit);
            float se = 0.5f * wsum(e);
            accg += 1.f / (1.f + se);
        }
        if (lane == 0) out[(size_t)h * nseq + s] = 0.25f * accg;
    }
}

// ---------------------------------------------------------------------------
// Launch
// ---------------------------------------------------------------------------
extern "C" void kernel_launch(void* const* d_in, const int* in_sizes, int n_in,
                              void* d_out, int out_size)
{
    const float* hidden = (const float*)d_in[0];
    const float* Wq     = (const float*)d_in[1];
    const float* bq     = (const float*)d_in[2];
    const float* Wk     = (const float*)d_in[3];
    const float* qw     = (const float*)d_in[4];
    const float* kw     = (const float*)d_in[5];
    const float* bvec   = (const float*)d_in[6];
    const float* kbase  = (const float*)d_in[7];

    const int nseq = in_sizes[0] / DIN_;

    __half* hb;  cudaGetSymbolAddress((void**)&hb, g_hbuf);
    __half* wb;  cudaGetSymbolAddress((void**)&wb, g_wbuf);

    {
        int n4 = nseq * DIN_ / 4;
        cvt_fp16<<<(n4 + 255) / 256, 256>>>((const float4*)hidden, (uint2*)hb, n4);
        n4 = NQ_ * DIN_ / 4;
        cvt_fp16<<<(n4 + 255) / 256, 256>>>((const float4*)Wq, (uint2*)wb, n4);
        n4 = NK_ * DIN_ / 4;
        cvt_fp16<<<(n4 + 255) / 256, 256>>>((const float4*)Wk,
                                            (uint2*)(wb + (size_t)NQ_ * DIN_), n4);
    }

    cudaFuncSetAttribute(gemm_qk, cudaFuncAttributeMaxDynamicSharedMemorySize, SMEM_TOTAL);

    dim3 ggrid(NTOT_ / BN, nseq / BM);   // 20 x 256
    gemm_qk<<<ggrid, 256, SMEM_TOTAL>>>(bq);

    epilogue_kernel<<<nseq / TOK_PER_BLK, 256>>>((float*)d_out, bvec, kbase, qw, kw, nseq);
}

// round 10
// speedup vs baseline: 1.8452x; 1.0343x over previous
#include <cuda_runtime.h>
#include <cuda_fp16.h>
#include <cstdint>

// ---------------------------------------------------------------------------
// Problem constants
// ---------------------------------------------------------------------------
#define DIN_   2048
#define NQ_    4096
#define NK_    1024
#define NTOT_  5120
#define DHEAD_ 128
#define NHEAD_ 8
#define NGROUP_ 4
#define SINK_  16
#define SMAX_  32768

__device__ __half g_qh[(size_t)SMAX_ * NQ_];     // 256 MB fp16 q scratch
__device__ __half g_kh[(size_t)SMAX_ * NK_];     // 64 MB  fp16 k scratch
__device__ __half g_hbuf[(size_t)SMAX_ * DIN_];  // 128 MB fp16 hidden
__device__ __half g_wbuf[(size_t)NTOT_ * DIN_];  // 20 MB  fp16 [Wq;Wk]

// ---------------------------------------------------------------------------
// fp32 -> fp16 conversion (RN), vectorized
// ---------------------------------------------------------------------------
__global__ void __launch_bounds__(256) cvt_fp16(const float4* __restrict__ src,
                                                uint2* __restrict__ dst, int n4)
{
    int i = blockIdx.x * blockDim.x + threadIdx.x;
    if (i < n4) {
        float4 v = src[i];
        __half2 h0 = __floats2half2_rn(v.x, v.y);
        __half2 h1 = __floats2half2_rn(v.z, v.w);
        uint2 o;
        o.x = *reinterpret_cast<uint32_t*>(&h0);
        o.y = *reinterpret_cast<uint32_t*>(&h1);
        dst[i] = o;
    }
}

// ---------------------------------------------------------------------------
// GEMM: C[S,5120] = hidden[S,2048] @ [Wq;Wk]^T (+bq on q part), fp16 in/out
// legacy mma.sync m16n8k16 (f32 accum), ldmatrix frags.
// BM=128 BN=128 BK=64, 3-stage ring (96 KB) -> 2 CTAs/SM so the second CTA's
// MMAs cover the first CTA's stage-boundary bubbles. Warp tile 64x32.
// ---------------------------------------------------------------------------
#define BM 128
#define BN 128
#define BK 64
#define NSTAGE 3
#define A_BYTES (128 * 128)             // 128 rows x 64 fp16
#define B_BYTES (128 * 128)
#define SLOT_BYTES (A_BYTES + B_BYTES)  // 32 KB
#define SMEM_TOTAL (NSTAGE * SLOT_BYTES)   // 96 KB

__device__ __forceinline__ uint32_t smem_to_u32(const void* p) {
    uint32_t a;
    asm("{ .reg .u64 t; cvta.to.shared.u64 t, %1; cvt.u32.u64 %0, t; }" : "=r"(a) : "l"(p));
    return a;
}

__device__ __forceinline__ void cp16s(uint32_t dst, const __half* src) {
    asm volatile("cp.async.cg.shared.global [%0], [%1], 16;\n" :: "r"(dst), "l"(src));
}

__device__ __forceinline__ void ldsm_x4(uint32_t& r0, uint32_t& r1, uint32_t& r2,
                                        uint32_t& r3, uint32_t addr) {
    asm volatile("ldmatrix.sync.aligned.m8n8.x4.shared.b16 {%0,%1,%2,%3}, [%4];"
                 : "=r"(r0), "=r"(r1), "=r"(r2), "=r"(r3) : "r"(addr));
}

__device__ __forceinline__ void mma_f16(float c[4], const uint32_t a[4],
                                        const uint32_t b0, const uint32_t b1) {
    asm volatile(
        "mma.sync.aligned.m16n8k16.row.col.f32.f16.f16.f32 "
        "{%0,%1,%2,%3}, {%4,%5,%6,%7}, {%8,%9}, {%0,%1,%2,%3};\n"
        : "+f"(c[0]), "+f"(c[1]), "+f"(c[2]), "+f"(c[3])
        : "r"(a[0]), "r"(a[1]), "r"(a[2]), "r"(a[3]), "r"(b0), "r"(b1));
}

__device__ __forceinline__ uint32_t swz(int row, int chunk) {
    return (uint32_t)(row * 128 + ((chunk ^ (row & 7)) << 4));
}

__global__ void __launch_bounds__(256, 2) gemm_qk(const float* __restrict__ bq)
{
    extern __shared__ char smem[];
    const uint32_t sbase = smem_to_u32(smem);
    const int tid = threadIdx.x;
    const int lane = tid & 31, wid = tid >> 5;
    const int wm = wid >> 2, wn = wid & 3;     // 2x4 warp grid, warp tile 64x32
    const int gid = lane >> 2, tig = lane & 3;

    const int n0 = blockIdx.x * BN;
    const int m0 = blockIdx.y * BM;
    const bool isq = (n0 < NQ_);
    const __half* wrow = g_wbuf + (size_t)n0 * DIN_;
    const __half* arow = g_hbuf + (size_t)m0 * DIN_;

    float acc[4][4][4];
#pragma unroll
    for (int a = 0; a < 4; a++)
#pragma unroll
        for (int b = 0; b < 4; b++)
#pragma unroll
            for (int c = 0; c < 4; c++) acc[a][b][c] = 0.f;

    // ldmatrix per-lane source rows/chunks (stage-invariant parts)
    const int arow_l   = wm * 64 + (lane & 15);                     // + tm*16
    const int achunk_l = lane >> 4;                                 // + 2*ks
    const int brow_l   = wn * 32 + (lane & 7) + ((lane & 16) >> 1); // + np*16
    const int bchunk_l = (lane >> 3) & 1;                           // + 2*ks

    auto load_stage = [&](int s) {
        const uint32_t slot = sbase + (uint32_t)(s % NSTAGE) * SLOT_BYTES;
        const int k0 = s * BK;
#pragma unroll
        for (int i = 0; i < 4; i++) {          // A: 128 rows x 8 chunks = 1024
            int id = tid + i * 256;
            int r = id >> 3, c = id & 7;
            cp16s(slot + swz(r, c), arow + (size_t)r * DIN_ + k0 + c * 8);
        }
#pragma unroll
        for (int i = 0; i < 4; i++) {          // B: 128 rows x 8 chunks = 1024
            int id = tid + i * 256;
            int r = id >> 3, c = id & 7;
            cp16s(slot + A_BYTES + swz(r, c), wrow + (size_t)r * DIN_ + k0 + c * 8);
        }
        asm volatile("cp.async.commit_group;\n");
    };

    load_stage(0);
    load_stage(1);

    const int NSTEPS = DIN_ / BK;  // 32
    for (int s = 0; s < NSTEPS; s++) {
        if (s < NSTEPS - 1) asm volatile("cp.async.wait_group 1;\n" ::: "memory");
        else                asm volatile("cp.async.wait_group 0;\n" ::: "memory");
        __syncthreads();

        const uint32_t slot = sbase + (uint32_t)(s % NSTAGE) * SLOT_BYTES;
#pragma unroll
        for (int ks = 0; ks < 4; ks++) {       // 4 x k16 per stage
            uint32_t af[4][4], bf[2][4];
#pragma unroll
            for (int tm = 0; tm < 4; tm++)
                ldsm_x4(af[tm][0], af[tm][1], af[tm][2], af[tm][3],
                        slot + swz(arow_l + tm * 16, 2 * ks + achunk_l));
#pragma unroll
            for (int np = 0; np < 2; np++)
                ldsm_x4(bf[np][0], bf[np][1], bf[np][2], bf[np][3],
                        slot + A_BYTES + swz(brow_l + np * 16, 2 * ks + bchunk_l));
#pragma unroll
            for (int tm = 0; tm < 4; tm++)
#pragma unroll
                for (int np = 0; np < 2; np++) {
                    mma_f16(acc[tm][2 * np],     af[tm], bf[np][0], bf[np][1]);
                    mma_f16(acc[tm][2 * np + 1], af[tm], bf[np][2], bf[np][3]);
                }
        }

        if (s + 2 < NSTEPS) load_stage(s + 2);
    }

    // ---- store fp16 (+bq on q part)
    float bq0[4], bq1[4];
#pragma unroll
    for (int tn = 0; tn < 4; tn++) {
        int col = n0 + wn * 32 + tn * 8 + 2 * tig;
        bq0[tn] = isq ? __ldg(bq + col) : 0.f;
        bq1[tn] = isq ? __ldg(bq + col + 1) : 0.f;
    }
    __half* obase = isq ? g_qh : g_kh;
    const int ld = isq ? NQ_ : NK_;
    const int cb = isq ? n0 : (n0 - NQ_);

#pragma unroll
    for (int tm = 0; tm < 4; tm++) {
#pragma unroll
        for (int tn = 0; tn < 4; tn++) {
            int r = m0 + wm * 64 + tm * 16 + gid;
            int c = cb + wn * 32 + tn * 8 + 2 * tig;
            __half2 v0 = __floats2half2_rn(acc[tm][tn][0] + bq0[tn], acc[tm][tn][1] + bq1[tn]);
            __half2 v1 = __floats2half2_rn(acc[tm][tn][2] + bq0[tn], acc[tm][tn][3] + bq1[tn]);
            *reinterpret_cast<__half2*>(obase + (size_t)r * ld + c) = v0;
            *reinterpret_cast<__half2*>(obase + (size_t)(r + 8) * ld + c) = v1;
        }
    }
}

// ---------------------------------------------------------------------------
// Epilogue (unchanged from R9): fp16 scratch reads; rq/rk folded out of the
// reductions; concurrent qss/dtt/sink reductions; butterfly for sinks.
// ---------------------------------------------------------------------------
#define TOK_PER_BLK 16

__device__ __forceinline__ float wsum(float v) {
    v += __shfl_xor_sync(0xffffffffu, v, 16);
    v += __shfl_xor_sync(0xffffffffu, v, 8);
    v += __shfl_xor_sync(0xffffffffu, v, 4);
    v += __shfl_xor_sync(0xffffffffu, v, 2);
    v += __shfl_xor_sync(0xffffffffu, v, 1);
    return v;
}

__device__ __forceinline__ void ld4h(float o[4], const __half* p) {
    uint2 r = *reinterpret_cast<const uint2*>(p);
    __half2 h0 = *reinterpret_cast<__half2*>(&r.x);
    __half2 h1 = *reinterpret_cast<__half2*>(&r.y);
    float2 f0 = __half22float2(h0), f1 = __half22float2(h1);
    o[0] = f0.x; o[1] = f0.y; o[2] = f1.x; o[3] = f1.y;
}

__global__ void __launch_bounds__(256) epilogue_kernel(
    float* __restrict__ out, const float* __restrict__ bvec,
    const float* __restrict__ k_base, const float* __restrict__ qw,
    const float* __restrict__ kw, int nseq)
{
    const int lane = threadIdx.x & 31;
    const int h = threadIdx.x >> 5;
    const float inv_d = 0.08838834764831845f;

    float qwr[4], kwr[4];
#pragma unroll
    for (int j = 0; j < 4; j++) {
        qwr[j] = qw[4 * lane + j];
        kwr[j] = kw[4 * lane + j];
    }
    float kbq[SINK_][4];
#pragma unroll
    for (int t = 0; t < SINK_; t++)
#pragma unroll
        for (int j = 0; j < 4; j++)
            kbq[t][j] = k_base[(size_t)(h * SINK_ + t) * DHEAD_ + 4 * lane + j] * qwr[j];

    float bb[4];
#pragma unroll
    for (int g = 0; g < NGROUP_; g++) bb[g] = bvec[h * NGROUP_ + g];

    const bool up16 = (lane & 16) != 0;
    const bool up8  = (lane & 8) != 0;
    const bool up4  = (lane & 4) != 0;
    const bool up2  = (lane & 2) != 0;

    for (int tt = 0; tt < TOK_PER_BLK; tt++) {
        const int s = blockIdx.x * TOK_PER_BLK + tt;

        float kd[4];
        ld4h(kd, g_kh + (size_t)s * NK_ + h * DHEAD_ + 4 * lane);
        float kss_p = kd[0]*kd[0] + kd[1]*kd[1] + kd[2]*kd[2] + kd[3]*kd[3];
        float kdq[4];
#pragma unroll
        for (int j = 0; j < 4; j++) kdq[j] = kd[j] * kwr[j] * qwr[j];
        float kss = wsum(kss_p);
        float rk = rsqrtf(kss * (1.0f / DHEAD_) + 1e-6f);

        float accg = 0.f;
#pragma unroll
        for (int g = 0; g < NGROUP_; g++) {
            float qd[4];
            ld4h(qd, g_qh + (size_t)s * NQ_ + h * (NGROUP_ * DHEAD_) + g * DHEAD_ + 4 * lane);

            float qss_p = qd[0]*qd[0] + qd[1]*qd[1] + qd[2]*qd[2] + qd[3]*qd[3];
            float dtt_p = kdq[0]*qd[0] + kdq[1]*qd[1] + kdq[2]*qd[2] + kdq[3]*qd[3];
            float p[SINK_];
#pragma unroll
            for (int t = 0; t < SINK_; t++)
                p[t] = kbq[t][0]*qd[0] + kbq[t][1]*qd[1] + kbq[t][2]*qd[2] + kbq[t][3]*qd[3];

            float qss = wsum(qss_p);
            float dtt = wsum(dtt_p);

            float v8[8];
#pragma unroll
            for (int i = 0; i < 8; i++) {
                float sd  = up16 ? p[i] : p[8 + i];
                float kp2 = up16 ? p[8 + i] : p[i];
                v8[i] = kp2 + __shfl_xor_sync(0xffffffffu, sd, 16);
            }
            float v4[4];
#pragma unroll
            for (int i = 0; i < 4; i++) {
                float sd  = up8 ? v8[i] : v8[4 + i];
                float kp2 = up8 ? v8[4 + i] : v8[i];
                v4[i] = kp2 + __shfl_xor_sync(0xffffffffu, sd, 8);
            }
            float v2[2];
#pragma unroll
            for (int i = 0; i < 2; i++) {
                float sd  = up4 ? v4[i] : v4[2 + i];
                float kp2 = up4 ? v4[2 + i] : v4[i];
                v2[i] = kp2 + __shfl_xor_sync(0xffffffffu, sd, 4);
            }
            float sd1 = up2 ? v2[0] : v2[1];
            float kp1 = up2 ? v2[1] : v2[0];
            float v1 = kp1 + __shfl_xor_sync(0xffffffffu, sd1, 2);
            float S = v1 + __shfl_xor_sync(0xffffffffu, v1, 1);

            float rq = rsqrtf(qss * (1.0f / DHEAD_) + 1e-6f);
            float logit = rk * rq * dtt * inv_d + 2.f * bb[g];

            float e = __expf(rq * S * inv_d - logit);
            float se = 0.5f * wsum(e);
            accg += 1.f / (1.f + se);
        }
        if (lane == 0) out[(size_t)h * nseq + s] = 0.25f * accg;
    }
}

// ---------------------------------------------------------------------------
// Launch
// ---------------------------------------------------------------------------
extern "C" void kernel_launch(void* const* d_in, const int* in_sizes, int n_in,
                              void* d_out, int out_size)
{
    const float* hidden = (const float*)d_in[0];
    const float* Wq     = (const float*)d_in[1];
    const float* bq     = (const float*)d_in[2];
    const float* Wk     = (const float*)d_in[3];
    const float* qw     = (const float*)d_in[4];
    const float* kw     = (const float*)d_in[5];
    const float* bvec   = (const float*)d_in[6];
    const float* kbase  = (const float*)d_in[7];

    const int nseq = in_sizes[0] / DIN_;

    __half* hb;  cudaGetSymbolAddress((void**)&hb, g_hbuf);
    __half* wb;  cudaGetSymbolAddress((void**)&wb, g_wbuf);

    {
        int n4 = nseq * DIN_ / 4;
        cvt_fp16<<<(n4 + 255) / 256, 256>>>((const float4*)hidden, (uint2*)hb, n4);
        n4 = NQ_ * DIN_ / 4;
        cvt_fp16<<<(n4 + 255) / 256, 256>>>((const float4*)Wq, (uint2*)wb, n4);
        n4 = NK_ * DIN_ / 4;
        cvt_fp16<<<(n4 + 255) / 256, 256>>>((const float4*)Wk,
                                            (uint2*)(wb + (size_t)NQ_ * DIN_), n4);
    }

    cudaFuncSetAttribute(gemm_qk, cudaFuncAttributeMaxDynamicSharedMemorySize, SMEM_TOTAL);

    dim3 ggrid(NTOT_ / BN, nseq / BM);   // 40 x 256
    gemm_qk<<<ggrid, 256, SMEM_TOTAL>>>(bq);

    epilogue_kernel<<<nseq / TOK_PER_BLK, 256>>>((float*)d_out, bvec, kbase, qw, kw, nseq);
}

// round 11
// speedup vs baseline: 1.9793x; 1.0727x over previous
#include <cuda_runtime.h>
#include <cuda_fp16.h>
#include <cstdint>

// ---------------------------------------------------------------------------
// Problem constants
// ---------------------------------------------------------------------------
#define DIN_   2048
#define NQ_    4096
#define NK_    1024
#define NTOT_  5120
#define DHEAD_ 128
#define NHEAD_ 8
#define NGROUP_ 4
#define SINK_  16
#define SMAX_  32768

__device__ __half g_qh[(size_t)SMAX_ * NQ_];     // 256 MB fp16 q scratch
__device__ __half g_kh[(size_t)SMAX_ * NK_];     // 64 MB  fp16 k scratch
__device__ __half g_hbuf[(size_t)SMAX_ * DIN_];  // 128 MB fp16 hidden
__device__ __half g_wbuf[(size_t)NTOT_ * DIN_];  // 20 MB  fp16 [Wq;Wk]

// ---------------------------------------------------------------------------
// fp32 -> fp16 conversion (RN), vectorized
// ---------------------------------------------------------------------------
__global__ void __launch_bounds__(256) cvt_fp16(const float4* __restrict__ src,
                                                uint2* __restrict__ dst, int n4)
{
    int i = blockIdx.x * blockDim.x + threadIdx.x;
    if (i < n4) {
        float4 v = src[i];
        __half2 h0 = __floats2half2_rn(v.x, v.y);
        __half2 h1 = __floats2half2_rn(v.z, v.w);
        uint2 o;
        o.x = *reinterpret_cast<uint32_t*>(&h0);
        o.y = *reinterpret_cast<uint32_t*>(&h1);
        dst[i] = o;
    }
}

// ---------------------------------------------------------------------------
// GEMM (unchanged from R10): mma.sync m16n8k16 fp16, BM=128 BN=128 BK=64,
// 3-stage ring (96 KB), 2 CTAs/SM, warp tile 64x32.
// ---------------------------------------------------------------------------
#define BM 128
#define BN 128
#define BK 64
#define NSTAGE 3
#define A_BYTES (128 * 128)
#define B_BYTES (128 * 128)
#define SLOT_BYTES (A_BYTES + B_BYTES)
#define SMEM_TOTAL (NSTAGE * SLOT_BYTES)   // 96 KB

__device__ __forceinline__ uint32_t smem_to_u32(const void* p) {
    uint32_t a;
    asm("{ .reg .u64 t; cvta.to.shared.u64 t, %1; cvt.u32.u64 %0, t; }" : "=r"(a) : "l"(p));
    return a;
}

__device__ __forceinline__ void cp16s(uint32_t dst, const __half* src) {
    asm volatile("cp.async.cg.shared.global [%0], [%1], 16;\n" :: "r"(dst), "l"(src));
}

__device__ __forceinline__ void ldsm_x4(uint32_t& r0, uint32_t& r1, uint32_t& r2,
                                        uint32_t& r3, uint32_t addr) {
    asm volatile("ldmatrix.sync.aligned.m8n8.x4.shared.b16 {%0,%1,%2,%3}, [%4];"
                 : "=r"(r0), "=r"(r1), "=r"(r2), "=r"(r3) : "r"(addr));
}

__device__ __forceinline__ void mma_f16(float c[4], const uint32_t a[4],
                                        const uint32_t b0, const uint32_t b1) {
    asm volatile(
        "mma.sync.aligned.m16n8k16.row.col.f32.f16.f16.f32 "
        "{%0,%1,%2,%3}, {%4,%5,%6,%7}, {%8,%9}, {%0,%1,%2,%3};\n"
        : "+f"(c[0]), "+f"(c[1]), "+f"(c[2]), "+f"(c[3])
        : "r"(a[0]), "r"(a[1]), "r"(a[2]), "r"(a[3]), "r"(b0), "r"(b1));
}

__device__ __forceinline__ uint32_t swz(int row, int chunk) {
    return (uint32_t)(row * 128 + ((chunk ^ (row & 7)) << 4));
}

__global__ void __launch_bounds__(256, 2) gemm_qk(const float* __restrict__ bq)
{
    extern __shared__ char smem[];
    const uint32_t sbase = smem_to_u32(smem);
    const int tid = threadIdx.x;
    const int lane = tid & 31, wid = tid >> 5;
    const int wm = wid >> 2, wn = wid & 3;
    const int gid = lane >> 2, tig = lane & 3;

    const int n0 = blockIdx.x * BN;
    const int m0 = blockIdx.y * BM;
    const bool isq = (n0 < NQ_);
    const __half* wrow = g_wbuf + (size_t)n0 * DIN_;
    const __half* arow = g_hbuf + (size_t)m0 * DIN_;

    float acc[4][4][4];
#pragma unroll
    for (int a = 0; a < 4; a++)
#pragma unroll
        for (int b = 0; b < 4; b++)
#pragma unroll
            for (int c = 0; c < 4; c++) acc[a][b][c] = 0.f;

    const int arow_l   = wm * 64 + (lane & 15);
    const int achunk_l = lane >> 4;
    const int brow_l   = wn * 32 + (lane & 7) + ((lane & 16) >> 1);
    const int bchunk_l = (lane >> 3) & 1;

    auto load_stage = [&](int s) {
        const uint32_t slot = sbase + (uint32_t)(s % NSTAGE) * SLOT_BYTES;
        const int k0 = s * BK;
#pragma unroll
        for (int i = 0; i < 4; i++) {
            int id = tid + i * 256;
            int r = id >> 3, c = id & 7;
            cp16s(slot + swz(r, c), arow + (size_t)r * DIN_ + k0 + c * 8);
        }
#pragma unroll
        for (int i = 0; i < 4; i++) {
            int id = tid + i * 256;
            int r = id >> 3, c = id & 7;
            cp16s(slot + A_BYTES + swz(r, c), wrow + (size_t)r * DIN_ + k0 + c * 8);
        }
        asm volatile("cp.async.commit_group;\n");
    };

    load_stage(0);
    load_stage(1);

    const int NSTEPS = DIN_ / BK;  // 32
    for (int s = 0; s < NSTEPS; s++) {
        if (s < NSTEPS - 1) asm volatile("cp.async.wait_group 1;\n" ::: "memory");
        else                asm volatile("cp.async.wait_group 0;\n" ::: "memory");
        __syncthreads();

        const uint32_t slot = sbase + (uint32_t)(s % NSTAGE) * SLOT_BYTES;
#pragma unroll
        for (int ks = 0; ks < 4; ks++) {
            uint32_t af[4][4], bf[2][4];
#pragma unroll
            for (int tm = 0; tm < 4; tm++)
                ldsm_x4(af[tm][0], af[tm][1], af[tm][2], af[tm][3],
                        slot + swz(arow_l + tm * 16, 2 * ks + achunk_l));
#pragma unroll
            for (int np = 0; np < 2; np++)
                ldsm_x4(bf[np][0], bf[np][1], bf[np][2], bf[np][3],
                        slot + A_BYTES + swz(brow_l + np * 16, 2 * ks + bchunk_l));
#pragma unroll
            for (int tm = 0; tm < 4; tm++)
#pragma unroll
                for (int np = 0; np < 2; np++) {
                    mma_f16(acc[tm][2 * np],     af[tm], bf[np][0], bf[np][1]);
                    mma_f16(acc[tm][2 * np + 1], af[tm], bf[np][2], bf[np][3]);
                }
        }

        if (s + 2 < NSTEPS) load_stage(s + 2);
    }

    // ---- store fp16 (+bq on q part)
    float bq0[4], bq1[4];
#pragma unroll
    for (int tn = 0; tn < 4; tn++) {
        int col = n0 + wn * 32 + tn * 8 + 2 * tig;
        bq0[tn] = isq ? __ldg(bq + col) : 0.f;
        bq1[tn] = isq ? __ldg(bq + col + 1) : 0.f;
    }
    __half* obase = isq ? g_qh : g_kh;
    const int ld = isq ? NQ_ : NK_;
    const int cb = isq ? n0 : (n0 - NQ_);

#pragma unroll
    for (int tm = 0; tm < 4; tm++) {
#pragma unroll
        for (int tn = 0; tn < 4; tn++) {
            int r = m0 + wm * 64 + tm * 16 + gid;
            int c = cb + wn * 32 + tn * 8 + 2 * tig;
            __half2 v0 = __floats2half2_rn(acc[tm][tn][0] + bq0[tn], acc[tm][tn][1] + bq1[tn]);
            __half2 v1 = __floats2half2_rn(acc[tm][tn][2] + bq0[tn], acc[tm][tn][3] + bq1[tn]);
            *reinterpret_cast<__half2*>(obase + (size_t)r * ld + c) = v0;
            *reinterpret_cast<__half2*>(obase + (size_t)(r + 8) * ld + c) = v1;
        }
    }
}

// ---------------------------------------------------------------------------
// Epilogue: cp.async-staged token rows (4-deep smem ring, 10KB/token) so all
// q/k reads are LDS; math identical to R9 (concurrent qss/dtt/sink reductions).
// ---------------------------------------------------------------------------
#define ETOK 32
#define ESTAGE 4
#define EQB (NQ_ * 2)                  // 8192 B q row
#define EKB (NK_ * 2)                  // 2048 B k row
#define ESLOT (EQB + EKB)              // 10240 B
#define EPI_SMEM (ESTAGE * ESLOT)      // 40960 B

__device__ __forceinline__ float wsum(float v) {
    v += __shfl_xor_sync(0xffffffffu, v, 16);
    v += __shfl_xor_sync(0xffffffffu, v, 8);
    v += __shfl_xor_sync(0xffffffffu, v, 4);
    v += __shfl_xor_sync(0xffffffffu, v, 2);
    v += __shfl_xor_sync(0xffffffffu, v, 1);
    return v;
}

__device__ __forceinline__ void ld4h_s(float o[4], uint32_t a) {
    uint32_t r0, r1;
    asm volatile("ld.shared.v2.b32 {%0,%1}, [%2];" : "=r"(r0), "=r"(r1) : "r"(a));
    __half2 h0 = *reinterpret_cast<__half2*>(&r0);
    __half2 h1 = *reinterpret_cast<__half2*>(&r1);
    float2 f0 = __half22float2(h0), f1 = __half22float2(h1);
    o[0] = f0.x; o[1] = f0.y; o[2] = f1.x; o[3] = f1.y;
}

__global__ void __launch_bounds__(256) epilogue_kernel(
    float* __restrict__ out, const float* __restrict__ bvec,
    const float* __restrict__ k_base, const float* __restrict__ qw,
    const float* __restrict__ kw, int nseq)
{
    extern __shared__ char esm[];
    const uint32_t sbase = smem_to_u32(esm);
    const int tid = threadIdx.x;
    const int lane = tid & 31;
    const int h = tid >> 5;
    const float inv_d = 0.08838834764831845f;
    const int tok0 = blockIdx.x * ETOK;

    float qwr[4], kwr[4];
#pragma unroll
    for (int j = 0; j < 4; j++) {
        qwr[j] = qw[4 * lane + j];
        kwr[j] = kw[4 * lane + j];
    }
    float kbq[SINK_][4];
#pragma unroll
    for (int t = 0; t < SINK_; t++)
#pragma unroll
        for (int j = 0; j < 4; j++)
            kbq[t][j] = k_base[(size_t)(h * SINK_ + t) * DHEAD_ + 4 * lane + j] * qwr[j];

    float bb[4];
#pragma unroll
    for (int g = 0; g < NGROUP_; g++) bb[g] = bvec[h * NGROUP_ + g];

    const bool up16 = (lane & 16) != 0;
    const bool up8  = (lane & 8) != 0;
    const bool up4  = (lane & 4) != 0;
    const bool up2  = (lane & 2) != 0;

    auto load_tok = [&](int i) {
        const int s = tok0 + i;
        const uint32_t slot = sbase + (uint32_t)(i % ESTAGE) * ESLOT;
        const __half* qsrc = g_qh + (size_t)s * NQ_;
        const __half* ksrc = g_kh + (size_t)s * NK_;
        cp16s(slot + (uint32_t)tid * 16, qsrc + tid * 8);
        cp16s(slot + (uint32_t)(tid + 256) * 16, qsrc + (tid + 256) * 8);
        if (tid < 128) cp16s(slot + EQB + (uint32_t)tid * 16, ksrc + tid * 8);
        asm volatile("cp.async.commit_group;\n");
    };

    load_tok(0);
    load_tok(1);
    load_tok(2);

    for (int i = 0; i < ETOK; i++) {
        if (i < ETOK - 2)       asm volatile("cp.async.wait_group 2;\n" ::: "memory");
        else if (i == ETOK - 2) asm volatile("cp.async.wait_group 1;\n" ::: "memory");
        else                    asm volatile("cp.async.wait_group 0;\n" ::: "memory");
        __syncthreads();

        if (i + 3 < ETOK) load_tok(i + 3);   // overwrites slot (i-1)%4: all done with it

        const uint32_t slot = sbase + (uint32_t)(i % ESTAGE) * ESLOT;

        // ---- k row
        float kd[4];
        ld4h_s(kd, slot + EQB + (uint32_t)(h * DHEAD_ + 4 * lane) * 2);
        float kss_p = kd[0]*kd[0] + kd[1]*kd[1] + kd[2]*kd[2] + kd[3]*kd[3];
        float kdq[4];
#pragma unroll
        for (int j = 0; j < 4; j++) kdq[j] = kd[j] * kwr[j] * qwr[j];
        float kss = wsum(kss_p);
        float rk = rsqrtf(kss * (1.0f / DHEAD_) + 1e-6f);

        float accg = 0.f;
#pragma unroll
        for (int g = 0; g < NGROUP_; g++) {
            float qd[4];
            ld4h_s(qd, slot + (uint32_t)(h * (NGROUP_ * DHEAD_) + g * DHEAD_ + 4 * lane) * 2);

            float qss_p = qd[0]*qd[0] + qd[1]*qd[1] + qd[2]*qd[2] + qd[3]*qd[3];
            float dtt_p = kdq[0]*qd[0] + kdq[1]*qd[1] + kdq[2]*qd[2] + kdq[3]*qd[3];
            float p[SINK_];
#pragma unroll
            for (int t = 0; t < SINK_; t++)
                p[t] = kbq[t][0]*qd[0] + kbq[t][1]*qd[1] + kbq[t][2]*qd[2] + kbq[t][3]*qd[3];

            float qss = wsum(qss_p);
            float dtt = wsum(dtt_p);

            float v8[8];
#pragma unroll
            for (int ii = 0; ii < 8; ii++) {
                float sd  = up16 ? p[ii] : p[8 + ii];
                float kp2 = up16 ? p[8 + ii] : p[ii];
                v8[ii] = kp2 + __shfl_xor_sync(0xffffffffu, sd, 16);
            }
            float v4[4];
#pragma unroll
            for (int ii = 0; ii < 4; ii++) {
                float sd  = up8 ? v8[ii] : v8[4 + ii];
                float kp2 = up8 ? v8[4 + ii] : v8[ii];
                v4[ii] = kp2 + __shfl_xor_sync(0xffffffffu, sd, 8);
            }
            float v2[2];
#pragma unroll
            for (int ii = 0; ii < 2; ii++) {
                float sd  = up4 ? v4[ii] : v4[2 + ii];
                float kp2 = up4 ? v4[2 + ii] : v4[ii];
                v2[ii] = kp2 + __shfl_xor_sync(0xffffffffu, sd, 4);
            }
            float sd1 = up2 ? v2[0] : v2[1];
            float kp1 = up2 ? v2[1] : v2[0];
            float v1 = kp1 + __shfl_xor_sync(0xffffffffu, sd1, 2);
            float S = v1 + __shfl_xor_sync(0xffffffffu, v1, 1);

            float rq = rsqrtf(qss * (1.0f / DHEAD_) + 1e-6f);
            float logit = rk * rq * dtt * inv_d + 2.f * bb[g];

            float e = __expf(rq * S * inv_d - logit);
            float se = 0.5f * wsum(e);
            accg += 1.f / (1.f + se);
        }
        if (lane == 0) out[(size_t)h * nseq + tok0 + i] = 0.25f * accg;
    }
}

// ---------------------------------------------------------------------------
// Launch
// ---------------------------------------------------------------------------
extern "C" void kernel_launch(void* const* d_in, const int* in_sizes, int n_in,
                              void* d_out, int out_size)
{
    const float* hidden = (const float*)d_in[0];
    const float* Wq     = (const float*)d_in[1];
    const float* bq     = (const float*)d_in[2];
    const float* Wk     = (const float*)d_in[3];
    const float* qw     = (const float*)d_in[4];
    const float* kw     = (const float*)d_in[5];
    const float* bvec   = (const float*)d_in[6];
    const float* kbase  = (const float*)d_in[7];

    const int nseq = in_sizes[0] / DIN_;

    __half* hb;  cudaGetSymbolAddress((void**)&hb, g_hbuf);
    __half* wb;  cudaGetSymbolAddress((void**)&wb, g_wbuf);

    {
        int n4 = nseq * DIN_ / 4;
        cvt_fp16<<<(n4 + 255) / 256, 256>>>((const float4*)hidden, (uint2*)hb, n4);
        n4 = NQ_ * DIN_ / 4;
        cvt_fp16<<<(n4 + 255) / 256, 256>>>((const float4*)Wq, (uint2*)wb, n4);
        n4 = NK_ * DIN_ / 4;
        cvt_fp16<<<(n4 + 255) / 256, 256>>>((const float4*)Wk,
                                            (uint2*)(wb + (size_t)NQ_ * DIN_), n4);
    }

    cudaFuncSetAttribute(gemm_qk, cudaFuncAttributeMaxDynamicSharedMemorySize, SMEM_TOTAL);

    dim3 ggrid(NTOT_ / BN, nseq / BM);   // 40 x 256
    gemm_qk<<<ggrid, 256, SMEM_TOTAL>>>(bq);

    epilogue_kernel<<<nseq / ETOK, 256, EPI_SMEM>>>((float*)d_out, bvec, kbase, qw, kw, nseq);
}

// round 12
// speedup vs baseline: 1.9958x; 1.0084x over previous
#include <cuda_runtime.h>
#include <cuda_fp16.h>
#include <cstdint>

// ---------------------------------------------------------------------------
// Problem constants
// ---------------------------------------------------------------------------
#define DIN_   2048
#define NQ_    4096
#define NK_    1024
#define NTOT_  5120
#define DHEAD_ 128
#define NHEAD_ 8
#define NGROUP_ 4
#define SINK_  16
#define SMAX_  32768
#define NCHUNK 4

__device__ __half g_qh[(size_t)SMAX_ * NQ_];     // 256 MB fp16 q scratch
__device__ __half g_kh[(size_t)SMAX_ * NK_];     // 64 MB  fp16 k scratch
__device__ __half g_hbuf[(size_t)SMAX_ * DIN_];  // 128 MB fp16 hidden
__device__ __half g_wbuf[(size_t)NTOT_ * DIN_];  // 20 MB  fp16 [Wq;Wk]

// ---------------------------------------------------------------------------
// fp32 -> fp16 conversion (RN), vectorized
// ---------------------------------------------------------------------------
__global__ void __launch_bounds__(256) cvt_fp16(const float4* __restrict__ src,
                                                uint2* __restrict__ dst, int n4)
{
    int i = blockIdx.x * blockDim.x + threadIdx.x;
    if (i < n4) {
        float4 v = src[i];
        __half2 h0 = __floats2half2_rn(v.x, v.y);
        __half2 h1 = __floats2half2_rn(v.z, v.w);
        uint2 o;
        o.x = *reinterpret_cast<uint32_t*>(&h0);
        o.y = *reinterpret_cast<uint32_t*>(&h1);
        dst[i] = o;
    }
}

// ---------------------------------------------------------------------------
// GEMM (math identical to R10/R11): mma.sync m16n8k16 fp16, BM=128 BN=128
// BK=64, 3-stage ring (96 KB), 2 CTAs/SM, warp tile 64x32. m_base = token
// offset of this chunk.
// ---------------------------------------------------------------------------
#define BM 128
#define BN 128
#define BK 64
#define NSTAGE 3
#define A_BYTES (128 * 128)
#define B_BYTES (128 * 128)
#define SLOT_BYTES (A_BYTES + B_BYTES)
#define SMEM_TOTAL (NSTAGE * SLOT_BYTES)   // 96 KB

__device__ __forceinline__ uint32_t smem_to_u32(const void* p) {
    uint32_t a;
    asm("{ .reg .u64 t; cvta.to.shared.u64 t, %1; cvt.u32.u64 %0, t; }" : "=r"(a) : "l"(p));
    return a;
}

__device__ __forceinline__ void cp16s(uint32_t dst, const __half* src) {
    asm volatile("cp.async.cg.shared.global [%0], [%1], 16;\n" :: "r"(dst), "l"(src));
}

__device__ __forceinline__ void ldsm_x4(uint32_t& r0, uint32_t& r1, uint32_t& r2,
                                        uint32_t& r3, uint32_t addr) {
    asm volatile("ldmatrix.sync.aligned.m8n8.x4.shared.b16 {%0,%1,%2,%3}, [%4];"
                 : "=r"(r0), "=r"(r1), "=r"(r2), "=r"(r3) : "r"(addr));
}

__device__ __forceinline__ void mma_f16(float c[4], const uint32_t a[4],
                                        const uint32_t b0, const uint32_t b1) {
    asm volatile(
        "mma.sync.aligned.m16n8k16.row.col.f32.f16.f16.f32 "
        "{%0,%1,%2,%3}, {%4,%5,%6,%7}, {%8,%9}, {%0,%1,%2,%3};\n"
        : "+f"(c[0]), "+f"(c[1]), "+f"(c[2]), "+f"(c[3])
        : "r"(a[0]), "r"(a[1]), "r"(a[2]), "r"(a[3]), "r"(b0), "r"(b1));
}

__device__ __forceinline__ uint32_t swz(int row, int chunk) {
    return (uint32_t)(row * 128 + ((chunk ^ (row & 7)) << 4));
}

__global__ void __launch_bounds__(256, 2) gemm_qk(const float* __restrict__ bq,
                                                  int m_base)
{
    extern __shared__ char smem[];
    const uint32_t sbase = smem_to_u32(smem);
    const int tid = threadIdx.x;
    const int lane = tid & 31, wid = tid >> 5;
    const int wm = wid >> 2, wn = wid & 3;
    const int gid = lane >> 2, tig = lane & 3;

    const int n0 = blockIdx.x * BN;
    const int m0 = m_base + blockIdx.y * BM;
    const bool isq = (n0 < NQ_);
    const __half* wrow = g_wbuf + (size_t)n0 * DIN_;
    const __half* arow = g_hbuf + (size_t)m0 * DIN_;

    float acc[4][4][4];
#pragma unroll
    for (int a = 0; a < 4; a++)
#pragma unroll
        for (int b = 0; b < 4; b++)
#pragma unroll
            for (int c = 0; c < 4; c++) acc[a][b][c] = 0.f;

    const int arow_l   = wm * 64 + (lane & 15);
    const int achunk_l = lane >> 4;
    const int brow_l   = wn * 32 + (lane & 7) + ((lane & 16) >> 1);
    const int bchunk_l = (lane >> 3) & 1;

    auto load_stage = [&](int s) {
        const uint32_t slot = sbase + (uint32_t)(s % NSTAGE) * SLOT_BYTES;
        const int k0 = s * BK;
#pragma unroll
        for (int i = 0; i < 4; i++) {
            int id = tid + i * 256;
            int r = id >> 3, c = id & 7;
            cp16s(slot + swz(r, c), arow + (size_t)r * DIN_ + k0 + c * 8);
        }
#pragma unroll
        for (int i = 0; i < 4; i++) {
            int id = tid + i * 256;
            int r = id >> 3, c = id & 7;
            cp16s(slot + A_BYTES + swz(r, c), wrow + (size_t)r * DIN_ + k0 + c * 8);
        }
        asm volatile("cp.async.commit_group;\n");
    };

    load_stage(0);
    load_stage(1);

    const int NSTEPS = DIN_ / BK;  // 32
    for (int s = 0; s < NSTEPS; s++) {
        if (s < NSTEPS - 1) asm volatile("cp.async.wait_group 1;\n" ::: "memory");
        else                asm volatile("cp.async.wait_group 0;\n" ::: "memory");
        __syncthreads();

        const uint32_t slot = sbase + (uint32_t)(s % NSTAGE) * SLOT_BYTES;
#pragma unroll
        for (int ks = 0; ks < 4; ks++) {
            uint32_t af[4][4], bf[2][4];
#pragma unroll
            for (int tm = 0; tm < 4; tm++)
                ldsm_x4(af[tm][0], af[tm][1], af[tm][2], af[tm][3],
                        slot + swz(arow_l + tm * 16, 2 * ks + achunk_l));
#pragma unroll
            for (int np = 0; np < 2; np++)
                ldsm_x4(bf[np][0], bf[np][1], bf[np][2], bf[np][3],
                        slot + A_BYTES + swz(brow_l + np * 16, 2 * ks + bchunk_l));
#pragma unroll
            for (int tm = 0; tm < 4; tm++)
#pragma unroll
                for (int np = 0; np < 2; np++) {
                    mma_f16(acc[tm][2 * np],     af[tm], bf[np][0], bf[np][1]);
                    mma_f16(acc[tm][2 * np + 1], af[tm], bf[np][2], bf[np][3]);
                }
        }

        if (s + 2 < NSTEPS) load_stage(s + 2);
    }

    // ---- store fp16 (+bq on q part)
    float bq0[4], bq1[4];
#pragma unroll
    for (int tn = 0; tn < 4; tn++) {
        int col = n0 + wn * 32 + tn * 8 + 2 * tig;
        bq0[tn] = isq ? __ldg(bq + col) : 0.f;
        bq1[tn] = isq ? __ldg(bq + col + 1) : 0.f;
    }
    __half* obase = isq ? g_qh : g_kh;
    const int ld = isq ? NQ_ : NK_;
    const int cb = isq ? n0 : (n0 - NQ_);

#pragma unroll
    for (int tm = 0; tm < 4; tm++) {
#pragma unroll
        for (int tn = 0; tn < 4; tn++) {
            int r = m0 + wm * 64 + tm * 16 + gid;
            int c = cb + wn * 32 + tn * 8 + 2 * tig;
            __half2 v0 = __floats2half2_rn(acc[tm][tn][0] + bq0[tn], acc[tm][tn][1] + bq1[tn]);
            __half2 v1 = __floats2half2_rn(acc[tm][tn][2] + bq0[tn], acc[tm][tn][3] + bq1[tn]);
            *reinterpret_cast<__half2*>(obase + (size_t)r * ld + c) = v0;
            *reinterpret_cast<__half2*>(obase + (size_t)(r + 8) * ld + c) = v1;
        }
    }
}

// ---------------------------------------------------------------------------
// Epilogue (math identical to R11): cp.async-staged token rows, 3-slot ring
// (30 KB) with depth-2 prefetch; concurrent qss/dtt/sink reductions.
// ---------------------------------------------------------------------------
#define ETOK 32
#define ESTAGE 3
#define EQB (NQ_ * 2)
#define EKB (NK_ * 2)
#define ESLOT (EQB + EKB)              // 10240 B
#define EPI_SMEM (ESTAGE * ESLOT)      // 30720 B

__device__ __forceinline__ float wsum(float v) {
    v += __shfl_xor_sync(0xffffffffu, v, 16);
    v += __shfl_xor_sync(0xffffffffu, v, 8);
    v += __shfl_xor_sync(0xffffffffu, v, 4);
    v += __shfl_xor_sync(0xffffffffu, v, 2);
    v += __shfl_xor_sync(0xffffffffu, v, 1);
    return v;
}

__device__ __forceinline__ void ld4h_s(float o[4], uint32_t a) {
    uint32_t r0, r1;
    asm volatile("ld.shared.v2.b32 {%0,%1}, [%2];" : "=r"(r0), "=r"(r1) : "r"(a));
    __half2 h0 = *reinterpret_cast<__half2*>(&r0);
    __half2 h1 = *reinterpret_cast<__half2*>(&r1);
    float2 f0 = __half22float2(h0), f1 = __half22float2(h1);
    o[0] = f0.x; o[1] = f0.y; o[2] = f1.x; o[3] = f1.y;
}

__global__ void __launch_bounds__(256) epilogue_kernel(
    float* __restrict__ out, const float* __restrict__ bvec,
    const float* __restrict__ k_base, const float* __restrict__ qw,
    const float* __restrict__ kw, int nseq, int tok_base)
{
    extern __shared__ char esm[];
    const uint32_t sbase = smem_to_u32(esm);
    const int tid = threadIdx.x;
    const int lane = tid & 31;
    const int h = tid >> 5;
    const float inv_d = 0.08838834764831845f;
    const int tok0 = tok_base + blockIdx.x * ETOK;

    float qwr[4], kwr[4];
#pragma unroll
    for (int j = 0; j < 4; j++) {
        qwr[j] = qw[4 * lane + j];
        kwr[j] = kw[4 * lane + j];
    }
    float kbq[SINK_][4];
#pragma unroll
    for (int t = 0; t < SINK_; t++)
#pragma unroll
        for (int j = 0; j < 4; j++)
            kbq[t][j] = k_base[(size_t)(h * SINK_ + t) * DHEAD_ + 4 * lane + j] * qwr[j];

    float bb[4];
#pragma unroll
    for (int g = 0; g < NGROUP_; g++) bb[g] = bvec[h * NGROUP_ + g];

    const bool up16 = (lane & 16) != 0;
    const bool up8  = (lane & 8) != 0;
    const bool up4  = (lane & 4) != 0;
    const bool up2  = (lane & 2) != 0;

    auto load_tok = [&](int i) {
        const int s = tok0 + i;
        const uint32_t slot = sbase + (uint32_t)(i % ESTAGE) * ESLOT;
        const __half* qsrc = g_qh + (size_t)s * NQ_;
        const __half* ksrc = g_kh + (size_t)s * NK_;
        cp16s(slot + (uint32_t)tid * 16, qsrc + tid * 8);
        cp16s(slot + (uint32_t)(tid + 256) * 16, qsrc + (tid + 256) * 8);
        if (tid < 128) cp16s(slot + EQB + (uint32_t)tid * 16, ksrc + tid * 8);
        asm volatile("cp.async.commit_group;\n");
    };

    load_tok(0);
    load_tok(1);

    for (int i = 0; i < ETOK; i++) {
        if (i < ETOK - 1) asm volatile("cp.async.wait_group 1;\n" ::: "memory");
        else              asm volatile("cp.async.wait_group 0;\n" ::: "memory");
        __syncthreads();

        if (i + 2 < ETOK) load_tok(i + 2);   // slot (i+2)%3 == (i-1)%3, done

        const uint32_t slot = sbase + (uint32_t)(i % ESTAGE) * ESLOT;

        float kd[4];
        ld4h_s(kd, slot + EQB + (uint32_t)(h * DHEAD_ + 4 * lane) * 2);
        float kss_p = kd[0]*kd[0] + kd[1]*kd[1] + kd[2]*kd[2] + kd[3]*kd[3];
        float kdq[4];
#pragma unroll
        for (int j = 0; j < 4; j++) kdq[j] = kd[j] * kwr[j] * qwr[j];
        float kss = wsum(kss_p);
        float rk = rsqrtf(kss * (1.0f / DHEAD_) + 1e-6f);

        float accg = 0.f;
#pragma unroll
        for (int g = 0; g < NGROUP_; g++) {
            float qd[4];
            ld4h_s(qd, slot + (uint32_t)(h * (NGROUP_ * DHEAD_) + g * DHEAD_ + 4 * lane) * 2);

            float qss_p = qd[0]*qd[0] + qd[1]*qd[1] + qd[2]*qd[2] + qd[3]*qd[3];
            float dtt_p = kdq[0]*qd[0] + kdq[1]*qd[1] + kdq[2]*qd[2] + kdq[3]*qd[3];
            float p[SINK_];
#pragma unroll
            for (int t = 0; t < SINK_; t++)
                p[t] = kbq[t][0]*qd[0] + kbq[t][1]*qd[1] + kbq[t][2]*qd[2] + kbq[t][3]*qd[3];

            float qss = wsum(qss_p);
            float dtt = wsum(dtt_p);

            float v8[8];
#pragma unroll
            for (int ii = 0; ii < 8; ii++) {
                float sd  = up16 ? p[ii] : p[8 + ii];
                float kp2 = up16 ? p[8 + ii] : p[ii];
                v8[ii] = kp2 + __shfl_xor_sync(0xffffffffu, sd, 16);
            }
            float v4[4];
#pragma unroll
            for (int ii = 0; ii < 4; ii++) {
                float sd  = up8 ? v8[ii] : v8[4 + ii];
                float kp2 = up8 ? v8[4 + ii] : v8[ii];
                v4[ii] = kp2 + __shfl_xor_sync(0xffffffffu, sd, 8);
            }
            float v2[2];
#pragma unroll
            for (int ii = 0; ii < 2; ii++) {
                float sd  = up4 ? v4[ii] : v4[2 + ii];
                float kp2 = up4 ? v4[2 + ii] : v4[ii];
                v2[ii] = kp2 + __shfl_xor_sync(0xffffffffu, sd, 4);
            }
            float sd1 = up2 ? v2[0] : v2[1];
            float kp1 = up2 ? v2[1] : v2[0];
            float v1 = kp1 + __shfl_xor_sync(0xffffffffu, sd1, 2);
            float S = v1 + __shfl_xor_sync(0xffffffffu, v1, 1);

            float rq = rsqrtf(qss * (1.0f / DHEAD_) + 1e-6f);
            float logit = rk * rq * dtt * inv_d + 2.f * bb[g];

            float e = __expf(rq * S * inv_d - logit);
            float se = 0.5f * wsum(e);
            accg += 1.f / (1.f + se);
        }
        if (lane == 0) out[(size_t)h * nseq + tok0 + i] = 0.25f * accg;
    }
}

// ---------------------------------------------------------------------------
// Launch: chunked gemm/epilogue on forked streams so epilogue chunks fill the
// GEMM's wave-drain gaps. Fork/join via events (graph-capture legal).
// ---------------------------------------------------------------------------
extern "C" void kernel_launch(void* const* d_in, const int* in_sizes, int n_in,
                              void* d_out, int out_size)
{
    const float* hidden = (const float*)d_in[0];
    const float* Wq     = (const float*)d_in[1];
    const float* bq     = (const float*)d_in[2];
    const float* Wk     = (const float*)d_in[3];
    const float* qw     = (const float*)d_in[4];
    const float* kw     = (const float*)d_in[5];
    const float* bvec   = (const float*)d_in[6];
    const float* kbase  = (const float*)d_in[7];

    const int nseq = in_sizes[0] / DIN_;
    const int chunk = nseq / NCHUNK;

    // one-time resources (created on the first, non-captured correctness call)
    static cudaStream_t s1 = nullptr;
    static cudaEvent_t evRoot, evW, evE;
    static cudaEvent_t evG[NCHUNK];
    if (s1 == nullptr) {
        cudaStreamCreateWithFlags(&s1, cudaStreamNonBlocking);
        cudaEventCreateWithFlags(&evRoot, cudaEventDisableTiming);
        cudaEventCreateWithFlags(&evW, cudaEventDisableTiming);
        cudaEventCreateWithFlags(&evE, cudaEventDisableTiming);
        for (int c = 0; c < NCHUNK; c++)
            cudaEventCreateWithFlags(&evG[c], cudaEventDisableTiming);
        cudaFuncSetAttribute(gemm_qk, cudaFuncAttributeMaxDynamicSharedMemorySize, SMEM_TOTAL);
    }

    __half* hb;  cudaGetSymbolAddress((void**)&hb, g_hbuf);
    __half* wb;  cudaGetSymbolAddress((void**)&wb, g_wbuf);

    // fork s1 from the capture stream
    cudaEventRecord(evRoot, 0);
    cudaStreamWaitEvent(s1, evRoot, 0);

    // s1: weight conversions (parallel with hidden conversion on s0)
    {
        int n4 = NQ_ * DIN_ / 4;
        cvt_fp16<<<(n4 + 255) / 256, 256, 0, s1>>>((const float4*)Wq, (uint2*)wb, n4);
        n4 = NK_ * DIN_ / 4;
        cvt_fp16<<<(n4 + 255) / 256, 256, 0, s1>>>((const float4*)Wk,
                                                   (uint2*)(wb + (size_t)NQ_ * DIN_), n4);
        cudaEventRecord(evW, s1);
    }

    // s0: hidden conversion, then gemm chunks
    {
        int n4 = nseq * DIN_ / 4;
        cvt_fp16<<<(n4 + 255) / 256, 256>>>((const float4*)hidden, (uint2*)hb, n4);
    }
    cudaStreamWaitEvent(0, evW, 0);

    dim3 ggrid(NTOT_ / BN, chunk / BM);   // 40 x 64 per chunk
    for (int c = 0; c < NCHUNK; c++) {
        gemm_qk<<<ggrid, 256, SMEM_TOTAL>>>(bq, c * chunk);
        cudaEventRecord(evG[c], 0);
        cudaStreamWaitEvent(s1, evG[c], 0);
        epilogue_kernel<<<chunk / ETOK, 256, EPI_SMEM, s1>>>(
            (float*)d_out, bvec, kbase, qw, kw, nseq, c * chunk);
    }

    // join s1 back into the capture stream
    cudaEventRecord(evE, s1);
    cudaStreamWaitEvent(0, evE, 0);
}

// round 13
// speedup vs baseline: 2.0441x; 1.0242x over previous
#include <cuda_runtime.h>
#include <cuda_fp16.h>
#include <cstdint>

// ---------------------------------------------------------------------------
// Problem constants
// ---------------------------------------------------------------------------
#define DIN_   2048
#define NQ_    4096
#define NK_    1024
#define NTOT_  5120
#define DHEAD_ 128
#define NHEAD_ 8
#define NGROUP_ 4
#define SINK_  16
#define SMAX_  32768
#define NCHUNK 4

__device__ __half g_qh[(size_t)SMAX_ * NQ_];     // 256 MB fp16 q scratch
__device__ __half g_kh[(size_t)SMAX_ * NK_];     // 64 MB  fp16 k scratch
__device__ __half g_hbuf[(size_t)SMAX_ * DIN_];  // 128 MB fp16 hidden
__device__ __half g_wbuf[(size_t)NTOT_ * DIN_];  // 20 MB  fp16 [Wq;Wk]

// ---------------------------------------------------------------------------
// fp32 -> fp16 conversion (RN), vectorized
// ---------------------------------------------------------------------------
__global__ void __launch_bounds__(256) cvt_fp16(const float4* __restrict__ src,
                                                uint2* __restrict__ dst, int n4)
{
    int i = blockIdx.x * blockDim.x + threadIdx.x;
    if (i < n4) {
        float4 v = src[i];
        __half2 h0 = __floats2half2_rn(v.x, v.y);
        __half2 h1 = __floats2half2_rn(v.z, v.w);
        uint2 o;
        o.x = *reinterpret_cast<uint32_t*>(&h0);
        o.y = *reinterpret_cast<uint32_t*>(&h1);
        dst[i] = o;
    }
}

// ---------------------------------------------------------------------------
// GEMM (unchanged math): mma.sync m16n8k16 fp16, BM=128 BN=128 BK=64,
// 3-stage ring (96 KB), 2 CTAs/SM, warp tile 64x32.
// ---------------------------------------------------------------------------
#define BM 128
#define BN 128
#define BK 64
#define NSTAGE 3
#define A_BYTES (128 * 128)
#define B_BYTES (128 * 128)
#define SLOT_BYTES (A_BYTES + B_BYTES)
#define SMEM_TOTAL (NSTAGE * SLOT_BYTES)   // 96 KB

__device__ __forceinline__ uint32_t smem_to_u32(const void* p) {
    uint32_t a;
    asm("{ .reg .u64 t; cvta.to.shared.u64 t, %1; cvt.u32.u64 %0, t; }" : "=r"(a) : "l"(p));
    return a;
}

__device__ __forceinline__ void cp16s(uint32_t dst, const __half* src) {
    asm volatile("cp.async.cg.shared.global [%0], [%1], 16;\n" :: "r"(dst), "l"(src));
}

__device__ __forceinline__ void ldsm_x4(uint32_t& r0, uint32_t& r1, uint32_t& r2,
                                        uint32_t& r3, uint32_t addr) {
    asm volatile("ldmatrix.sync.aligned.m8n8.x4.shared.b16 {%0,%1,%2,%3}, [%4];"
                 : "=r"(r0), "=r"(r1), "=r"(r2), "=r"(r3) : "r"(addr));
}

__device__ __forceinline__ void mma_f16(float c[4], const uint32_t a[4],
                                        const uint32_t b0, const uint32_t b1) {
    asm volatile(
        "mma.sync.aligned.m16n8k16.row.col.f32.f16.f16.f32 "
        "{%0,%1,%2,%3}, {%4,%5,%6,%7}, {%8,%9}, {%0,%1,%2,%3};\n"
        : "+f"(c[0]), "+f"(c[1]), "+f"(c[2]), "+f"(c[3])
        : "r"(a[0]), "r"(a[1]), "r"(a[2]), "r"(a[3]), "r"(b0), "r"(b1));
}

__device__ __forceinline__ uint32_t swz(int row, int chunk) {
    return (uint32_t)(row * 128 + ((chunk ^ (row & 7)) << 4));
}

__global__ void __launch_bounds__(256, 2) gemm_qk(const float* __restrict__ bq,
                                                  int m_base)
{
    extern __shared__ char smem[];
    const uint32_t sbase = smem_to_u32(smem);
    const int tid = threadIdx.x;
    const int lane = tid & 31, wid = tid >> 5;
    const int wm = wid >> 2, wn = wid & 3;
    const int gid = lane >> 2, tig = lane & 3;

    const int n0 = blockIdx.x * BN;
    const int m0 = m_base + blockIdx.y * BM;
    const bool isq = (n0 < NQ_);
    const __half* wrow = g_wbuf + (size_t)n0 * DIN_;
    const __half* arow = g_hbuf + (size_t)m0 * DIN_;

    float acc[4][4][4];
#pragma unroll
    for (int a = 0; a < 4; a++)
#pragma unroll
        for (int b = 0; b < 4; b++)
#pragma unroll
            for (int c = 0; c < 4; c++) acc[a][b][c] = 0.f;

    const int arow_l   = wm * 64 + (lane & 15);
    const int achunk_l = lane >> 4;
    const int brow_l   = wn * 32 + (lane & 7) + ((lane & 16) >> 1);
    const int bchunk_l = (lane >> 3) & 1;

    auto load_stage = [&](int s) {
        const uint32_t slot = sbase + (uint32_t)(s % NSTAGE) * SLOT_BYTES;
        const int k0 = s * BK;
#pragma unroll
        for (int i = 0; i < 4; i++) {
            int id = tid + i * 256;
            int r = id >> 3, c = id & 7;
            cp16s(slot + swz(r, c), arow + (size_t)r * DIN_ + k0 + c * 8);
        }
#pragma unroll
        for (int i = 0; i < 4; i++) {
            int id = tid + i * 256;
            int r = id >> 3, c = id & 7;
            cp16s(slot + A_BYTES + swz(r, c), wrow + (size_t)r * DIN_ + k0 + c * 8);
        }
        asm volatile("cp.async.commit_group;\n");
    };

    load_stage(0);
    load_stage(1);

    const int NSTEPS = DIN_ / BK;  // 32
    for (int s = 0; s < NSTEPS; s++) {
        if (s < NSTEPS - 1) asm volatile("cp.async.wait_group 1;\n" ::: "memory");
        else                asm volatile("cp.async.wait_group 0;\n" ::: "memory");
        __syncthreads();

        const uint32_t slot = sbase + (uint32_t)(s % NSTAGE) * SLOT_BYTES;
#pragma unroll
        for (int ks = 0; ks < 4; ks++) {
            uint32_t af[4][4], bf[2][4];
#pragma unroll
            for (int tm = 0; tm < 4; tm++)
                ldsm_x4(af[tm][0], af[tm][1], af[tm][2], af[tm][3],
                        slot + swz(arow_l + tm * 16, 2 * ks + achunk_l));
#pragma unroll
            for (int np = 0; np < 2; np++)
                ldsm_x4(bf[np][0], bf[np][1], bf[np][2], bf[np][3],
                        slot + A_BYTES + swz(brow_l + np * 16, 2 * ks + bchunk_l));
#pragma unroll
            for (int tm = 0; tm < 4; tm++)
#pragma unroll
                for (int np = 0; np < 2; np++) {
                    mma_f16(acc[tm][2 * np],     af[tm], bf[np][0], bf[np][1]);
                    mma_f16(acc[tm][2 * np + 1], af[tm], bf[np][2], bf[np][3]);
                }
        }

        if (s + 2 < NSTEPS) load_stage(s + 2);
    }

    float bq0[4], bq1[4];
#pragma unroll
    for (int tn = 0; tn < 4; tn++) {
        int col = n0 + wn * 32 + tn * 8 + 2 * tig;
        bq0[tn] = isq ? __ldg(bq + col) : 0.f;
        bq1[tn] = isq ? __ldg(bq + col + 1) : 0.f;
    }
    __half* obase = isq ? g_qh : g_kh;
    const int ld = isq ? NQ_ : NK_;
    const int cb = isq ? n0 : (n0 - NQ_);

#pragma unroll
    for (int tm = 0; tm < 4; tm++) {
#pragma unroll
        for (int tn = 0; tn < 4; tn++) {
            int r = m0 + wm * 64 + tm * 16 + gid;
            int c = cb + wn * 32 + tn * 8 + 2 * tig;
            __half2 v0 = __floats2half2_rn(acc[tm][tn][0] + bq0[tn], acc[tm][tn][1] + bq1[tn]);
            __half2 v1 = __floats2half2_rn(acc[tm][tn][2] + bq0[tn], acc[tm][tn][3] + bq1[tn]);
            *reinterpret_cast<__half2*>(obase + (size_t)r * ld + c) = v0;
            *reinterpret_cast<__half2*>(obase + (size_t)(r + 8) * ld + c) = v1;
        }
    }
}

// ---------------------------------------------------------------------------
// Epilogue v3: TOKEN-PAIR processing — dual independent reduction chains
// interleaved to hide shfl latency. kbq packed as __half2 (register relief).
// 3-deep pair ring (61 KB) of cp.async-staged token rows.
// ---------------------------------------------------------------------------
#define ETOK 32
#define EQB (NQ_ * 2)                  // 8192 B
#define EKB (NK_ * 2)                  // 2048 B
#define ETOKB (EQB + EKB)              // 10240 B per token
#define EPSLOT (2 * ETOKB)             // 20480 B per pair
#define EPI_SMEM (3 * EPSLOT)          // 61440 B

__device__ __forceinline__ void wsum2(float& a, float& b) {
#pragma unroll
    for (int m = 16; m >= 1; m >>= 1) {
        a += __shfl_xor_sync(0xffffffffu, a, m);
        b += __shfl_xor_sync(0xffffffffu, b, m);
    }
}

__device__ __forceinline__ void ld4h_s(float o[4], uint32_t a) {
    uint32_t r0, r1;
    asm volatile("ld.shared.v2.b32 {%0,%1}, [%2];" : "=r"(r0), "=r"(r1) : "r"(a));
    __half2 h0 = *reinterpret_cast<__half2*>(&r0);
    __half2 h1 = *reinterpret_cast<__half2*>(&r1);
    float2 f0 = __half22float2(h0), f1 = __half22float2(h1);
    o[0] = f0.x; o[1] = f0.y; o[2] = f1.x; o[3] = f1.y;
}

__global__ void __launch_bounds__(256) epilogue_kernel(
    float* __restrict__ out, const float* __restrict__ bvec,
    const float* __restrict__ k_base, const float* __restrict__ qw,
    const float* __restrict__ kw, int nseq, int tok_base)
{
    extern __shared__ char esm[];
    const uint32_t sbase = smem_to_u32(esm);
    const int tid = threadIdx.x;
    const int lane = tid & 31;
    const int h = tid >> 5;
    const float inv_d = 0.08838834764831845f;
    const int tok0 = tok_base + blockIdx.x * ETOK;

    float qwr[4], kwr[4];
#pragma unroll
    for (int j = 0; j < 4; j++) {
        qwr[j] = qw[4 * lane + j];
        kwr[j] = kw[4 * lane + j];
    }
    // kbq packed: kbq2[t][0]=(kb[d0]*qw, kb[d1]*qw), [t][1]=(d2,d3)
    __half2 kbq2[SINK_][2];
#pragma unroll
    for (int t = 0; t < SINK_; t++) {
        const float* kb = k_base + (size_t)(h * SINK_ + t) * DHEAD_ + 4 * lane;
        kbq2[t][0] = __floats2half2_rn(kb[0] * qwr[0], kb[1] * qwr[1]);
        kbq2[t][1] = __floats2half2_rn(kb[2] * qwr[2], kb[3] * qwr[3]);
    }

    float bb[4];
#pragma unroll
    for (int g = 0; g < NGROUP_; g++) bb[g] = bvec[h * NGROUP_ + g];

    const bool up16 = (lane & 16) != 0;
    const bool up8  = (lane & 8) != 0;
    const bool up4  = (lane & 4) != 0;
    const bool up2  = (lane & 2) != 0;

    auto load_pair = [&](int p) {
        const uint32_t slot = sbase + (uint32_t)(p % 3) * EPSLOT;
#pragma unroll
        for (int tt = 0; tt < 2; tt++) {
            const int s = tok0 + 2 * p + tt;
            const uint32_t tb = slot + (uint32_t)tt * ETOKB;
            const __half* qsrc = g_qh + (size_t)s * NQ_;
            const __half* ksrc = g_kh + (size_t)s * NK_;
            cp16s(tb + (uint32_t)tid * 16, qsrc + tid * 8);
            cp16s(tb + (uint32_t)(tid + 256) * 16, qsrc + (tid + 256) * 8);
            if (tid < 128) cp16s(tb + EQB + (uint32_t)tid * 16, ksrc + tid * 8);
        }
        asm volatile("cp.async.commit_group;\n");
    };

    load_pair(0);
    load_pair(1);

    const int NPAIR = ETOK / 2;   // 16
    for (int p = 0; p < NPAIR; p++) {
        if (p < NPAIR - 1) asm volatile("cp.async.wait_group 1;\n" ::: "memory");
        else               asm volatile("cp.async.wait_group 0;\n" ::: "memory");
        __syncthreads();

        if (p + 2 < NPAIR) load_pair(p + 2);   // slot (p+2)%3 == (p-1)%3, done

        const uint32_t slot = sbase + (uint32_t)(p % 3) * EPSLOT;

        // ---- k rows (both tokens)
        float kd[2][4], kdq[2][4], kss[2];
#pragma unroll
        for (int tt = 0; tt < 2; tt++) {
            ld4h_s(kd[tt], slot + (uint32_t)tt * ETOKB + EQB + (uint32_t)(h * DHEAD_ + 4 * lane) * 2);
            kss[tt] = kd[tt][0]*kd[tt][0] + kd[tt][1]*kd[tt][1]
                    + kd[tt][2]*kd[tt][2] + kd[tt][3]*kd[tt][3];
#pragma unroll
            for (int j = 0; j < 4; j++) kdq[tt][j] = kd[tt][j] * kwr[j] * qwr[j];
        }
        wsum2(kss[0], kss[1]);
        float rk[2];
#pragma unroll
        for (int tt = 0; tt < 2; tt++)
            rk[tt] = rsqrtf(kss[tt] * (1.0f / DHEAD_) + 1e-6f);

        float accg[2] = {0.f, 0.f};
#pragma unroll
        for (int g = 0; g < NGROUP_; g++) {
            float qd[2][4], qss[2], dtt[2];
#pragma unroll
            for (int tt = 0; tt < 2; tt++) {
                ld4h_s(qd[tt], slot + (uint32_t)tt * ETOKB
                       + (uint32_t)(h * (NGROUP_ * DHEAD_) + g * DHEAD_ + 4 * lane) * 2);
                qss[tt] = qd[tt][0]*qd[tt][0] + qd[tt][1]*qd[tt][1]
                        + qd[tt][2]*qd[tt][2] + qd[tt][3]*qd[tt][3];
                dtt[tt] = kdq[tt][0]*qd[tt][0] + kdq[tt][1]*qd[tt][1]
                        + kdq[tt][2]*qd[tt][2] + kdq[tt][3]*qd[tt][3];
            }

            float p2[2][SINK_];
#pragma unroll
            for (int t = 0; t < SINK_; t++) {
                float2 c0 = __half22float2(kbq2[t][0]);
                float2 c1 = __half22float2(kbq2[t][1]);
#pragma unroll
                for (int tt = 0; tt < 2; tt++)
                    p2[tt][t] = c0.x*qd[tt][0] + c0.y*qd[tt][1]
                              + c1.x*qd[tt][2] + c1.y*qd[tt][3];
            }

            wsum2(qss[0], qss[1]);
            wsum2(dtt[0], dtt[1]);

            // dual multi-value butterfly (interleaved chains)
            float v8[2][8];
#pragma unroll
            for (int ii = 0; ii < 8; ii++)
#pragma unroll
                for (int tt = 0; tt < 2; tt++) {
                    float sd  = up16 ? p2[tt][ii] : p2[tt][8 + ii];
                    float kp2 = up16 ? p2[tt][8 + ii] : p2[tt][ii];
                    v8[tt][ii] = kp2 + __shfl_xor_sync(0xffffffffu, sd, 16);
                }
            float v4[2][4];
#pragma unroll
            for (int ii = 0; ii < 4; ii++)
#pragma unroll
                for (int tt = 0; tt < 2; tt++) {
                    float sd  = up8 ? v8[tt][ii] : v8[tt][4 + ii];
                    float kp2 = up8 ? v8[tt][4 + ii] : v8[tt][ii];
                    v4[tt][ii] = kp2 + __shfl_xor_sync(0xffffffffu, sd, 8);
                }
            float v2[2][2];
#pragma unroll
            for (int ii = 0; ii < 2; ii++)
#pragma unroll
                for (int tt = 0; tt < 2; tt++) {
                    float sd  = up4 ? v4[tt][ii] : v4[tt][2 + ii];
                    float kp2 = up4 ? v4[tt][2 + ii] : v4[tt][ii];
                    v2[tt][ii] = kp2 + __shfl_xor_sync(0xffffffffu, sd, 4);
                }
            float S[2], e[2];
#pragma unroll
            for (int tt = 0; tt < 2; tt++) {
                float sd1 = up2 ? v2[tt][0] : v2[tt][1];
                float kp1 = up2 ? v2[tt][1] : v2[tt][0];
                float v1 = kp1 + __shfl_xor_sync(0xffffffffu, sd1, 2);
                S[tt] = v1 + __shfl_xor_sync(0xffffffffu, v1, 1);
            }
#pragma unroll
            for (int tt = 0; tt < 2; tt++) {
                float rq = rsqrtf(qss[tt] * (1.0f / DHEAD_) + 1e-6f);
                float logit = rk[tt] * rq * dtt[tt] * inv_d + 2.f * bb[g];
                e[tt] = __expf(rq * S[tt] * inv_d - logit);
            }
            wsum2(e[0], e[1]);
#pragma unroll
            for (int tt = 0; tt < 2; tt++)
                accg[tt] += 1.f / (1.f + 0.5f * e[tt]);
        }
        if (lane == 0) {
#pragma unroll
            for (int tt = 0; tt < 2; tt++)
                out[(size_t)h * nseq + tok0 + 2 * p + tt] = 0.25f * accg[tt];
        }
    }
}

// ---------------------------------------------------------------------------
// Launch: s2 converts hidden chunk-wise (gemm chunk c gated on cvt chunk c);
// s1 runs weight cvt + epilogue chunks. Fork/join via events.
// ---------------------------------------------------------------------------
extern "C" void kernel_launch(void* const* d_in, const int* in_sizes, int n_in,
                              void* d_out, int out_size)
{
    const float* hidden = (const float*)d_in[0];
    const float* Wq     = (const float*)d_in[1];
    const float* bq     = (const float*)d_in[2];
    const float* Wk     = (const float*)d_in[3];
    const float* qw     = (const float*)d_in[4];
    const float* kw     = (const float*)d_in[5];
    const float* bvec   = (const float*)d_in[6];
    const float* kbase  = (const float*)d_in[7];

    const int nseq = in_sizes[0] / DIN_;
    const int chunk = nseq / NCHUNK;

    static cudaStream_t s1 = nullptr, s2 = nullptr;
    static cudaEvent_t evRoot, evW, evE;
    static cudaEvent_t evG[NCHUNK], evC[NCHUNK];
    if (s1 == nullptr) {
        int lo, hi;
        cudaDeviceGetStreamPriorityRange(&lo, &hi);
        cudaStreamCreateWithPriority(&s1, cudaStreamNonBlocking, hi);
        cudaStreamCreateWithFlags(&s2, cudaStreamNonBlocking);
        cudaEventCreateWithFlags(&evRoot, cudaEventDisableTiming);
        cudaEventCreateWithFlags(&evW, cudaEventDisableTiming);
        cudaEventCreateWithFlags(&evE, cudaEventDisableTiming);
        for (int c = 0; c < NCHUNK; c++) {
            cudaEventCreateWithFlags(&evG[c], cudaEventDisableTiming);
            cudaEventCreateWithFlags(&evC[c], cudaEventDisableTiming);
        }
        cudaFuncSetAttribute(gemm_qk, cudaFuncAttributeMaxDynamicSharedMemorySize, SMEM_TOTAL);
        cudaFuncSetAttribute(epilogue_kernel, cudaFuncAttributeMaxDynamicSharedMemorySize, EPI_SMEM);
    }

    __half* hb;  cudaGetSymbolAddress((void**)&hb, g_hbuf);
    __half* wb;  cudaGetSymbolAddress((void**)&wb, g_wbuf);

    // fork
    cudaEventRecord(evRoot, 0);
    cudaStreamWaitEvent(s1, evRoot, 0);
    cudaStreamWaitEvent(s2, evRoot, 0);

    // s1: weight conversions
    {
        int n4 = NQ_ * DIN_ / 4;
        cvt_fp16<<<(n4 + 255) / 256, 256, 0, s1>>>((const float4*)Wq, (uint2*)wb, n4);
        n4 = NK_ * DIN_ / 4;
        cvt_fp16<<<(n4 + 255) / 256, 256, 0, s1>>>((const float4*)Wk,
                                                   (uint2*)(wb + (size_t)NQ_ * DIN_), n4);
        cudaEventRecord(evW, s1);
    }

    // s2: hidden conversion, chunk-wise
    {
        const int c4 = chunk * DIN_ / 4;
        for (int c = 0; c < NCHUNK; c++) {
            cvt_fp16<<<(c4 + 255) / 256, 256, 0, s2>>>(
                (const float4*)hidden + (size_t)c * c4,
                (uint2*)hb + (size_t)c * c4, c4);
            cudaEventRecord(evC[c], s2);
        }
    }

    // s0: gemm chunks; s1: epilogue chunks
    cudaStreamWaitEvent(0, evW, 0);
    dim3 ggrid(NTOT_ / BN, chunk / BM);   // 40 x 64 per chunk
    for (int c = 0; c < NCHUNK; c++) {
        cudaStreamWaitEvent(0, evC[c], 0);
        gemm_qk<<<ggrid, 256, SMEM_TOTAL>>>(bq, c * chunk);
        cudaEventRecord(evG[c], 0);
        cudaStreamWaitEvent(s1, evG[c], 0);
        epilogue_kernel<<<chunk / ETOK, 256, EPI_SMEM, s1>>>(
            (float*)d_out, bvec, kbase, qw, kw, nseq, c * chunk);
    }

    // join
    cudaEventRecord(evE, s1);
    cudaStreamWaitEvent(0, evE, 0);
}